// round 12
// baseline (speedup 1.0000x reference)
#include <cuda_runtime.h>
#include <cuda_fp16.h>
#include <cstdint>

#define Bn  8
#define Cc  256
#define HWn 4096

// ---- flash smem layout (half offsets) ----
#define QPH 264
#define VPH 72
#define PPH 72
#define OFF_Q  0
#define OFF_K0 16896
#define OFF_K1 33792
#define OFF_V0 50688
#define OFF_V1 69120
#define OFF_P0 87552
#define OFF_P1 92160
#define OFF_F  96768
#define F_MX 128
#define F_LS 256
#define SMEM_BYTES (OFF_F * 2 + 384 * 4)   // 195072 B

// ---- fp16 GEMM tiles (qkv/proj) ----
#define GP 264
#define GEMM_SMEM (2 * 128 * GP * 2)       // 135168 B

// ---------------- scratch -----------------------------------------------------
__device__ __half g_xnh[(size_t)Bn * HWn * Cc];
__device__ __half g_qwh[768 * 256];
__device__ __half g_pwh[256 * 256];
__device__ __half g_q [(size_t)Bn * HWn * Cc];
__device__ __half g_k [(size_t)Bn * HWn * Cc];
__device__ __half g_vt[(size_t)Bn * Cc * HWn];
__device__ __half g_aoh[(size_t)Bn * HWn * Cc];

// ---------------- helpers ------------------------------------------------------
__device__ __forceinline__ void mma16(float c[4], uint32_t a0, uint32_t a1, uint32_t a2,
                                      uint32_t a3, uint32_t b0, uint32_t b1) {
    asm("mma.sync.aligned.m16n8k16.row.col.f32.f16.f16.f32 "
        "{%0,%1,%2,%3},{%4,%5,%6,%7},{%8,%9},{%0,%1,%2,%3};"
        : "+f"(c[0]), "+f"(c[1]), "+f"(c[2]), "+f"(c[3])
        : "r"(a0), "r"(a1), "r"(a2), "r"(a3), "r"(b0), "r"(b1));
}
// fp16-accumulate variant: c[0] = rows 0-7 (two cols packed), c[1] = rows 8-15
__device__ __forceinline__ void mma16h(uint32_t c[2], uint32_t a0, uint32_t a1,
                                       uint32_t a2, uint32_t a3,
                                       uint32_t b0, uint32_t b1) {
    asm("mma.sync.aligned.m16n8k16.row.col.f16.f16.f16.f16 "
        "{%0,%1},{%2,%3,%4,%5},{%6,%7},{%0,%1};"
        : "+r"(c[0]), "+r"(c[1])
        : "r"(a0), "r"(a1), "r"(a2), "r"(a3), "r"(b0), "r"(b1));
}
__device__ __forceinline__ void ldsm4(uint32_t& r0, uint32_t& r1, uint32_t& r2,
                                      uint32_t& r3, uint32_t a) {
    asm volatile("ldmatrix.sync.aligned.m8n8.x4.shared.b16 {%0,%1,%2,%3}, [%4];"
        : "=r"(r0), "=r"(r1), "=r"(r2), "=r"(r3) : "r"(a));
}
#define H2U(x) (*(const uint32_t*)&(x))

__device__ __forceinline__ void cp16(void* dst, const void* src) {
    uint32_t d = (uint32_t)__cvta_generic_to_shared(dst);
    asm volatile("cp.async.cg.shared.global [%0], [%1], 16;\n" :: "r"(d), "l"(src));
}
__device__ __forceinline__ void cpcommit() { asm volatile("cp.async.commit_group;\n"); }
template<int N> __device__ __forceinline__ void cpwait() {
    asm volatile("cp.async.wait_group %0;\n" :: "n"(N));
}

// ---------------- GroupNorm (+ fused weight conversion blocks) -------------------
__global__ __launch_bounds__(512) void gn_kernel(const float* __restrict__ x,
                                                 const float* __restrict__ w,
                                                 const float* __restrict__ bv,
                                                 const float* __restrict__ qw,
                                                 const float* __restrict__ pw) {
    if (blockIdx.x >= 64) {
        // weight-conversion blocks: 384 x 512 = 196608 = 768*256 exactly
        int i = (blockIdx.x - 64) * 512 + threadIdx.x;
        g_qwh[i] = __float2half(qw[i]);
        if (i < 256 * 256) g_pwh[i] = __float2half(pw[i]);
        return;
    }

    __shared__ float sm[32][132];
    __shared__ float rs[16], rss[16], ws[32], bs[32];
    int bg = blockIdx.x, b = bg >> 3, g = bg & 7;
    const float* xb = x + ((size_t)b * Cc + (size_t)g * 32) * HWn;
    const int NEL = 32 * HWn;
    int tid = threadIdx.x;

    float s = 0.f, ss = 0.f;
    for (int i = tid; i < NEL; i += 512) {
        float v = xb[i];
        s += v; ss += v * v;
    }
    int lane = tid & 31, wid = tid >> 5;
    #pragma unroll
    for (int o = 16; o; o >>= 1) {
        s  += __shfl_down_sync(0xffffffffu, s, o);
        ss += __shfl_down_sync(0xffffffffu, ss, o);
    }
    if (lane == 0) { rs[wid] = s; rss[wid] = ss; }
    if (tid < 32) { ws[tid] = w[g * 32 + tid]; bs[tid] = bv[g * 32 + tid]; }
    __syncthreads();
    if (wid == 0) {
        s  = (lane < 16) ? rs[lane]  : 0.f;
        ss = (lane < 16) ? rss[lane] : 0.f;
        #pragma unroll
        for (int o = 8; o; o >>= 1) {
            s  += __shfl_down_sync(0xffffffffu, s, o);
            ss += __shfl_down_sync(0xffffffffu, ss, o);
        }
        if (lane == 0) { rs[0] = s; rss[0] = ss; }
    }
    __syncthreads();
    float mean = rs[0] / (float)NEL;
    float var  = rss[0] / (float)NEL - mean * mean;
    float rstd = rsqrtf(var + 1e-5f);

    __half* out = g_xnh + (size_t)b * HWn * Cc + g * 32;
    int c  = tid >> 4, pl = (tid & 15) * 8;
    int pl2 = tid >> 2, c8 = (tid & 3) * 8;

    for (int p0 = 0; p0 < HWn; p0 += 128) {
        float4 v0 = *(const float4*)(xb + (size_t)c * HWn + p0 + pl);
        float4 v1 = *(const float4*)(xb + (size_t)c * HWn + p0 + pl + 4);
        __syncthreads();
        *(float4*)&sm[c][pl]     = v0;
        *(float4*)&sm[c][pl + 4] = v1;
        __syncthreads();
        __half2 h[4];
        #pragma unroll
        for (int jj = 0; jj < 4; jj++) {
            int c0 = c8 + jj * 2;
            float a0 = (sm[c0][pl2]     - mean) * rstd * ws[c0]     + bs[c0];
            float a1 = (sm[c0 + 1][pl2] - mean) * rstd * ws[c0 + 1] + bs[c0 + 1];
            h[jj] = __floats2half2_rn(a0, a1);
        }
        *(uint4*)&out[(size_t)(p0 + pl2) * Cc + c8] = *(uint4*)h;
    }
}

// ---------------- fp16 NT GEMM core ----------------------------------------------
__device__ __forceinline__ void gemm16(const __half* __restrict__ Ag,
                                       const __half* __restrict__ Bg,
                                       __half* gsm, float acc[2][8][4]) {
    int t = threadIdx.x;
    #pragma unroll
    for (int i = 0; i < 16; i++) {
        int idx = t + 256 * i;
        int row = idx >> 5, pc = idx & 31;
        cp16(gsm + row * GP + pc * 8, Ag + (size_t)row * 256 + pc * 8);
        cp16(gsm + 128 * GP + row * GP + pc * 8, Bg + (size_t)row * 256 + pc * 8);
    }
    cpcommit();
    cpwait<0>();
    __syncthreads();

    int wid = t >> 5, lane = t & 31;
    int wm = (wid >> 1) * 32, wn = (wid & 1) * 64;
    uint32_t sb = (uint32_t)__cvta_generic_to_shared(gsm);
    uint32_t aA = sb + (uint32_t)((wm + (lane & 15)) * GP + (lane >> 4) * 8) * 2;
    uint32_t rowKV = (uint32_t)(((lane >> 4) << 3) + (lane & 7));
    uint32_t colHi = (uint32_t)(((lane >> 3) & 1) << 3);
    uint32_t aB = sb + (uint32_t)(128 * GP + (wn + rowKV) * GP + colHi) * 2;

    #pragma unroll
    for (int ks = 0; ks < 16; ks++) {
        uint32_t a[2][4];
        ldsm4(a[0][0], a[0][1], a[0][2], a[0][3], aA + ks * 32);
        ldsm4(a[1][0], a[1][1], a[1][2], a[1][3], aA + 16 * GP * 2 + ks * 32);
        #pragma unroll
        for (int ng = 0; ng < 4; ng++) {
            uint32_t b0, b1, b2, b3;
            ldsm4(b0, b1, b2, b3, aB + ng * (16 * GP * 2) + ks * 32);
            #pragma unroll
            for (int mt = 0; mt < 2; mt++) {
                mma16(acc[mt][ng * 2],     a[mt][0], a[mt][1], a[mt][2], a[mt][3], b0, b1);
                mma16(acc[mt][ng * 2 + 1], a[mt][0], a[mt][1], a[mt][2], a[mt][3], b2, b3);
            }
        }
    }
}

// ---------------- QKV GEMM ---------------------------------------------------------
__global__ __launch_bounds__(256) void qkv_kernel(const float* __restrict__ bias) {
    extern __shared__ __align__(16) __half gsm[];
    int b = blockIdx.z;
    int pm = blockIdx.y * 128;
    int on = blockIdx.x * 128;
    const __half* Ag = g_xnh + (size_t)b * HWn * Cc + (size_t)pm * Cc;
    const __half* Bg = g_qwh + (size_t)on * Cc;

    float acc[2][8][4] = {};
    gemm16(Ag, Bg, gsm, acc);

    int t = threadIdx.x, wid = t >> 5, lane = t & 31, g = lane >> 2, t4 = lane & 3;
    int wm = (wid >> 1) * 32, wn = (wid & 1) * 64;

    if (on < 512) {
        __half* dst = ((on < 256) ? g_q : g_k) + (size_t)b * HWn * Cc;
        int obase = on & 255;
        #pragma unroll
        for (int nt = 0; nt < 8; nt++) {
            int ocol = wn + nt * 8 + t4 * 2;
            float2 bb = *(const float2*)&bias[on + ocol];
            #pragma unroll
            for (int mt = 0; mt < 2; mt++) {
                int p0 = pm + wm + mt * 16 + g;
                __half2 v0 = __floats2half2_rn(acc[mt][nt][0] + bb.x, acc[mt][nt][1] + bb.y);
                __half2 v1 = __floats2half2_rn(acc[mt][nt][2] + bb.x, acc[mt][nt][3] + bb.y);
                *(__half2*)&dst[(size_t)p0 * Cc + obase + ocol]       = v0;
                *(__half2*)&dst[(size_t)(p0 + 8) * Cc + obase + ocol] = v1;
            }
        }
    } else {
        __half* dst = g_vt + (size_t)b * Cc * HWn;
        #pragma unroll
        for (int nt = 0; nt < 8; nt++) {
            int ocol = wn + nt * 8 + t4 * 2;
            int c0 = (on - 512) + ocol;
            float2 bb = *(const float2*)&bias[on + ocol];
            #pragma unroll
            for (int mt = 0; mt < 2; mt++) {
                int p0 = pm + wm + mt * 16 + g;
                dst[(size_t)c0 * HWn + p0]           = __float2half(acc[mt][nt][0] + bb.x);
                dst[(size_t)(c0 + 1) * HWn + p0]     = __float2half(acc[mt][nt][1] + bb.y);
                dst[(size_t)c0 * HWn + p0 + 8]       = __float2half(acc[mt][nt][2] + bb.x);
                dst[(size_t)(c0 + 1) * HWn + p0 + 8] = __float2half(acc[mt][nt][3] + bb.y);
            }
        }
    }
}

// ---------------- flash: warp-specialized; S-GEMM fp16 accumulate ----------------
__device__ __forceinline__ void copyK16(const __half* Kg, int kt, __half* kb, int t) {
    #pragma unroll
    for (int i = 0; i < 8; i++) {
        int idx = t + 256 * i;
        int row = idx >> 5, pc = idx & 31;
        cp16(kb + row * QPH + pc * 8, Kg + (size_t)(kt * 64 + row) * Cc + pc * 8);
    }
}
__device__ __forceinline__ void copyV16(const __half* Vtg, int kt, __half* vb, int t) {
    #pragma unroll
    for (int i = 0; i < 8; i++) {
        int idx = t + 256 * i;
        int c = idx >> 3, pc = idx & 7;
        cp16(vb + c * VPH + pc * 8, Vtg + (size_t)c * HWn + kt * 64 + pc * 8);
    }
}

__global__ void __launch_bounds__(512, 1) flash_kernel() {
    extern __shared__ __align__(16) __half smh[];
    float* smf = (float*)(smh + OFF_F);
    int b = blockIdx.y;
    int qbase = blockIdx.x * 64;
    const __half* Qg  = g_q  + (size_t)b * HWn * Cc + (size_t)qbase * Cc;
    const __half* Kg  = g_k  + (size_t)b * HWn * Cc;
    const __half* Vtg = g_vt + (size_t)b * Cc * HWn;

    int t = threadIdx.x;
    int wid = t >> 5, lane = t & 31, g = lane >> 2, t4 = lane & 3;
    bool isProd = (wid < 8);
    uint32_t sb = (uint32_t)__cvta_generic_to_shared(smh);
    uint32_t rowKV = (uint32_t)(((lane >> 4) << 3) + (lane & 7));
    uint32_t colHi = (uint32_t)(((lane >> 3) & 1) << 3);

    int mi = (wid & 7) >> 1, ni = wid & 1;
    int wm = mi * 16;
    int r0 = wm + g, r1 = r0 + 8;
    uint32_t aQ  = sb + (uint32_t)(OFF_Q  + (wm + (lane & 15)) * QPH + (lane >> 4) * 8) * 2;
    uint32_t aK0 = sb + (uint32_t)(OFF_K0 + (ni * 32 + rowKV) * QPH + colHi) * 2;
    uint32_t aK1 = sb + (uint32_t)(OFF_K1 + (ni * 32 + rowKV) * QPH + colHi) * 2;

    int cw = wid - 8;
    int cq = (cw > 0 ? cw : 0) >> 1, cc = cw & 1;
    int cr0 = cq * 16 + g, cr1 = cr0 + 8;
    uint32_t aP0 = sb + (uint32_t)(OFF_P0 + (cq * 16 + (lane & 15)) * PPH + (lane >> 4) * 8) * 2;
    uint32_t aP1 = sb + (uint32_t)(OFF_P1 + (cq * 16 + (lane & 15)) * PPH + (lane >> 4) * 8) * 2;
    uint32_t aV0 = sb + (uint32_t)(OFF_V0 + (cc * 128 + rowKV) * VPH + colHi) * 2;
    uint32_t aV1 = sb + (uint32_t)(OFF_V1 + (cc * 128 + rowKV) * VPH + colHi) * 2;

    float oacc[16][4] = {};
    float M0 = -1e30f, M1 = -1e30f, L0 = 0.f, L1 = 0.f;

    if (isProd) copyK16(Kg, 0, smh + OFF_K0, t);
    else        copyK16(Qg, 0, smh + OFF_Q, t - 256);
    cpcommit();
    cpwait<0>();
    __syncthreads();

    const float SCL = 0.09016844f;   // log2(e)/16

    for (int i = 0; i <= 64; i++) {
        if (isProd) {
            if (i < 63) {
                copyK16(Kg, i + 1, smh + (((i + 1) & 1) ? OFF_K1 : OFF_K0), t);
                cpcommit();
            }
            if (i < 64) {
                // ---- S(i) = Q K(i)^T, fp16 accumulation ----
                uint32_t kb = (i & 1) ? aK1 : aK0;
                uint32_t sacc2[4][2] = {};
                #pragma unroll
                for (int ks = 0; ks < 16; ks++) {
                    uint32_t q0, q1, q2, q3;
                    ldsm4(q0, q1, q2, q3, aQ + ks * 32);
                    #pragma unroll
                    for (int ntp = 0; ntp < 2; ntp++) {
                        uint32_t b0, b1, b2, b3;
                        ldsm4(b0, b1, b2, b3, kb + ntp * (16 * QPH * 2) + ks * 32);
                        mma16h(sacc2[ntp * 2],     q0, q1, q2, q3, b0, b1);
                        mma16h(sacc2[ntp * 2 + 1], q0, q1, q2, q3, b2, b3);
                    }
                }
                // unpack to fp32
                float sacc[4][4];
                #pragma unroll
                for (int nt = 0; nt < 4; nt++) {
                    float2 lo = __half22float2(*(const __half2*)&sacc2[nt][0]);
                    float2 hi = __half22float2(*(const __half2*)&sacc2[nt][1]);
                    sacc[nt][0] = lo.x; sacc[nt][1] = lo.y;
                    sacc[nt][2] = hi.x; sacc[nt][3] = hi.y;
                }
                // ---- softmax with cross-half max ----
                float mx0 = -1e30f, mx1 = -1e30f;
                #pragma unroll
                for (int nt = 0; nt < 4; nt++) {
                    #pragma unroll
                    for (int jj = 0; jj < 4; jj++) sacc[nt][jj] *= SCL;
                    mx0 = fmaxf(mx0, fmaxf(sacc[nt][0], sacc[nt][1]));
                    mx1 = fmaxf(mx1, fmaxf(sacc[nt][2], sacc[nt][3]));
                }
                mx0 = fmaxf(mx0, __shfl_xor_sync(0xffffffffu, mx0, 1));
                mx0 = fmaxf(mx0, __shfl_xor_sync(0xffffffffu, mx0, 2));
                mx1 = fmaxf(mx1, __shfl_xor_sync(0xffffffffu, mx1, 1));
                mx1 = fmaxf(mx1, __shfl_xor_sync(0xffffffffu, mx1, 2));
                if (t4 == 0) {
                    smf[F_MX + ni * 64 + r0] = mx0;
                    smf[F_MX + ni * 64 + r1] = mx1;
                }
                asm volatile("bar.sync 1, 256;" ::: "memory");
                float Mn0 = fmaxf(M0, fmaxf(mx0, smf[F_MX + (1 - ni) * 64 + r0]));
                float Mn1 = fmaxf(M1, fmaxf(mx1, smf[F_MX + (1 - ni) * 64 + r1]));
                float f0 = exp2f(M0 - Mn0), f1 = exp2f(M1 - Mn1);
                M0 = Mn0; M1 = Mn1;
                if (ni == 0 && t4 == 0) {
                    smf[(i & 1) * 64 + r0] = f0;
                    smf[(i & 1) * 64 + r1] = f1;
                }
                float s0 = 0.f, s1 = 0.f;
                __half* Pb = smh + ((i & 1) ? OFF_P1 : OFF_P0);
                #pragma unroll
                for (int nt = 0; nt < 4; nt++) {
                    float p00 = exp2f(sacc[nt][0] - Mn0);
                    float p01 = exp2f(sacc[nt][1] - Mn0);
                    float p10 = exp2f(sacc[nt][2] - Mn1);
                    float p11 = exp2f(sacc[nt][3] - Mn1);
                    s0 += p00 + p01; s1 += p10 + p11;
                    __half2 u0 = __floats2half2_rn(p00, p01);
                    __half2 u1 = __floats2half2_rn(p10, p11);
                    int ccol = ni * 32 + nt * 8 + t4 * 2;
                    *(__half2*)&Pb[r0 * PPH + ccol] = u0;
                    *(__half2*)&Pb[r1 * PPH + ccol] = u1;
                }
                s0 += __shfl_xor_sync(0xffffffffu, s0, 1);
                s0 += __shfl_xor_sync(0xffffffffu, s0, 2);
                s1 += __shfl_xor_sync(0xffffffffu, s1, 1);
                s1 += __shfl_xor_sync(0xffffffffu, s1, 2);
                L0 = L0 * f0 + s0;
                L1 = L1 * f1 + s1;
            } else {
                if (t4 == 0) {
                    smf[F_LS + ni * 64 + r0] = L0;
                    smf[F_LS + ni * 64 + r1] = L1;
                }
            }
        } else {
            if (i < 64) {
                copyV16(Vtg, i, smh + ((i & 1) ? OFF_V1 : OFF_V0), t - 256);
                cpcommit();
            }
            if (i >= 1) {
                int j = i - 1;
                float f0 = smf[(j & 1) * 64 + cr0];
                float f1 = smf[(j & 1) * 64 + cr1];
                bool nor = (f0 == 1.f) && (f1 == 1.f);
                if (__ballot_sync(0xffffffffu, nor) != 0xffffffffu) {
                    #pragma unroll
                    for (int q = 0; q < 16; q++) {
                        oacc[q][0] *= f0; oacc[q][1] *= f0;
                        oacc[q][2] *= f1; oacc[q][3] *= f1;
                    }
                }
                uint32_t aP = (j & 1) ? aP1 : aP0;
                uint32_t aV = (j & 1) ? aV1 : aV0;
                #pragma unroll
                for (int km = 0; km < 4; km++) {
                    uint32_t pa0, pa1, pa2, pa3;
                    ldsm4(pa0, pa1, pa2, pa3, aP + km * 32);
                    #pragma unroll
                    for (int ct = 0; ct < 8; ct++) {
                        uint32_t v0, v1, v2, v3;
                        ldsm4(v0, v1, v2, v3, aV + ct * (16 * VPH * 2) + km * 32);
                        mma16(oacc[ct * 2],     pa0, pa1, pa2, pa3, v0, v1);
                        mma16(oacc[ct * 2 + 1], pa0, pa1, pa2, pa3, v2, v3);
                    }
                }
            }
        }
        cpwait<0>();
        __syncthreads();
    }

    if (!isProd) {
        float Lt0 = smf[F_LS + cr0] + smf[F_LS + 64 + cr0];
        float Lt1 = smf[F_LS + cr1] + smf[F_LS + 64 + cr1];
        float inv0 = 1.0f / Lt0, inv1 = 1.0f / Lt1;
        __half* AO = g_aoh + (size_t)b * HWn * Cc;
        #pragma unroll
        for (int q = 0; q < 16; q++) {
            int ch = cc * 128 + q * 8 + t4 * 2;
            __half2 v0 = __floats2half2_rn(oacc[q][0] * inv0, oacc[q][1] * inv0);
            __half2 v1 = __floats2half2_rn(oacc[q][2] * inv1, oacc[q][3] * inv1);
            *(__half2*)&AO[(size_t)(qbase + cr0) * Cc + ch] = v0;
            *(__half2*)&AO[(size_t)(qbase + cr1) * Cc + ch] = v1;
        }
    }
}

// ---------------- proj GEMM (fp16) + residual ------------------------------------
__global__ __launch_bounds__(256) void proj_kernel(const float* __restrict__ x,
                                                   const float* __restrict__ pb,
                                                   float* __restrict__ out) {
    extern __shared__ __align__(16) __half gsm[];
    int b = blockIdx.z;
    int om = blockIdx.y * 128;
    int pn = blockIdx.x * 128;
    const __half* Ag = g_pwh + (size_t)om * Cc;
    const __half* Bg = g_aoh + (size_t)b * HWn * Cc + (size_t)pn * Cc;

    float acc[2][8][4] = {};
    gemm16(Ag, Bg, gsm, acc);

    int t = threadIdx.x, wid = t >> 5, lane = t & 31, g = lane >> 2, t4 = lane & 3;
    int wm = (wid >> 1) * 32, wn = (wid & 1) * 64;

    #pragma unroll
    for (int mt = 0; mt < 2; mt++) {
        int o0 = om + wm + mt * 16 + g;
        float b0 = pb[o0], b1 = pb[o0 + 8];
        #pragma unroll
        for (int nt = 0; nt < 8; nt++) {
            int p0 = pn + wn + nt * 8 + t4 * 2;
            size_t off0 = ((size_t)b * Cc + o0) * HWn + p0;
            size_t off1 = ((size_t)b * Cc + o0 + 8) * HWn + p0;
            float2 x0 = *(const float2*)&x[off0];
            float2 x1 = *(const float2*)&x[off1];
            float2 v0 = { acc[mt][nt][0] + b0 + x0.x, acc[mt][nt][1] + b0 + x0.y };
            float2 v1 = { acc[mt][nt][2] + b1 + x1.x, acc[mt][nt][3] + b1 + x1.y };
            *(float2*)&out[off0] = v0;
            *(float2*)&out[off1] = v1;
        }
    }
}

// ---------------- launch ---------------------------------------------------------
extern "C" void kernel_launch(void* const* d_in, const int* in_sizes, int n_in,
                              void* d_out, int out_size) {
    const float* x  = (const float*)d_in[0];
    const float* nw = (const float*)d_in[1];
    const float* nb = (const float*)d_in[2];
    const float* qw = (const float*)d_in[3];
    const float* qb = (const float*)d_in[4];
    const float* pw = (const float*)d_in[5];
    const float* pb = (const float*)d_in[6];
    float* out = (float*)d_out;

    cudaFuncSetAttribute(flash_kernel, cudaFuncAttributeMaxDynamicSharedMemorySize,
                         SMEM_BYTES);
    cudaFuncSetAttribute(qkv_kernel, cudaFuncAttributeMaxDynamicSharedMemorySize,
                         GEMM_SMEM);
    cudaFuncSetAttribute(proj_kernel, cudaFuncAttributeMaxDynamicSharedMemorySize,
                         GEMM_SMEM);

    gn_kernel<<<64 + 384, 512>>>(x, nw, nb, qw, pw);
    qkv_kernel<<<dim3(6, 32, 8), 256, GEMM_SMEM>>>(qb);
    flash_kernel<<<dim3(64, 8), 512, SMEM_BYTES>>>();
    proj_kernel<<<dim3(32, 2, 8), 256, GEMM_SMEM>>>(x, pb, out);
}

// round 13
// speedup vs baseline: 1.0855x; 1.0855x over previous
#include <cuda_runtime.h>
#include <cuda_fp16.h>
#include <cstdint>

#define Bn  8
#define Cc  256
#define HWn 4096

// ---- flash smem layout (half offsets) ----
#define QPH 264
#define VPH 72
#define PPH 72
#define OFF_Q  0
#define OFF_K0 16896
#define OFF_K1 33792
#define OFF_V0 50688
#define OFF_V1 69120
#define OFF_P0 87552
#define OFF_P1 92160
#define OFF_F  96768
#define F_MX 128
#define F_LS 256
#define SMEM_BYTES (OFF_F * 2 + 384 * 4)   // 195072 B

// ---- fp16 GEMM tiles (qkv/proj) ----
#define GP 264
#define GEMM_SMEM (2 * 128 * GP * 2)       // 135168 B

// ---------------- scratch -----------------------------------------------------
__device__ __half g_xnh[(size_t)Bn * HWn * Cc];
__device__ __half g_qwh[768 * 256];
__device__ __half g_pwh[256 * 256];
__device__ __half g_q [(size_t)Bn * HWn * Cc];
__device__ __half g_k [(size_t)Bn * HWn * Cc];
__device__ __half g_vt[(size_t)Bn * Cc * HWn];
__device__ __half g_aoh[(size_t)Bn * HWn * Cc];
__device__ float  g_op [(size_t)2 * Bn * HWn * Cc];   // partial O (2 halves), fp32
__device__ float2 g_ml [(size_t)2 * Bn * HWn];        // per-row (M, L) per half

// ---------------- helpers ------------------------------------------------------
__device__ __forceinline__ void mma16(float c[4], uint32_t a0, uint32_t a1, uint32_t a2,
                                      uint32_t a3, uint32_t b0, uint32_t b1) {
    asm("mma.sync.aligned.m16n8k16.row.col.f32.f16.f16.f32 "
        "{%0,%1,%2,%3},{%4,%5,%6,%7},{%8,%9},{%0,%1,%2,%3};"
        : "+f"(c[0]), "+f"(c[1]), "+f"(c[2]), "+f"(c[3])
        : "r"(a0), "r"(a1), "r"(a2), "r"(a3), "r"(b0), "r"(b1));
}
__device__ __forceinline__ void ldsm4(uint32_t& r0, uint32_t& r1, uint32_t& r2,
                                      uint32_t& r3, uint32_t a) {
    asm volatile("ldmatrix.sync.aligned.m8n8.x4.shared.b16 {%0,%1,%2,%3}, [%4];"
        : "=r"(r0), "=r"(r1), "=r"(r2), "=r"(r3) : "r"(a));
}
#define H2U(x) (*(const uint32_t*)&(x))

__device__ __forceinline__ void cp16(void* dst, const void* src) {
    uint32_t d = (uint32_t)__cvta_generic_to_shared(dst);
    asm volatile("cp.async.cg.shared.global [%0], [%1], 16;\n" :: "r"(d), "l"(src));
}
__device__ __forceinline__ void cpcommit() { asm volatile("cp.async.commit_group;\n"); }
template<int N> __device__ __forceinline__ void cpwait() {
    asm volatile("cp.async.wait_group %0;\n" :: "n"(N));
}

// ---------------- GroupNorm (+ fused weight conversion blocks) -------------------
__global__ __launch_bounds__(512) void gn_kernel(const float* __restrict__ x,
                                                 const float* __restrict__ w,
                                                 const float* __restrict__ bv,
                                                 const float* __restrict__ qw,
                                                 const float* __restrict__ pw) {
    if (blockIdx.x >= 64) {
        int i = (blockIdx.x - 64) * 512 + threadIdx.x;
        g_qwh[i] = __float2half(qw[i]);
        if (i < 256 * 256) g_pwh[i] = __float2half(pw[i]);
        return;
    }

    __shared__ float sm[32][132];
    __shared__ float rs[16], rss[16], ws[32], bs[32];
    int bg = blockIdx.x, b = bg >> 3, g = bg & 7;
    const float* xb = x + ((size_t)b * Cc + (size_t)g * 32) * HWn;
    const int NEL = 32 * HWn;
    int tid = threadIdx.x;

    float s = 0.f, ss = 0.f;
    for (int i = tid; i < NEL; i += 512) {
        float v = xb[i];
        s += v; ss += v * v;
    }
    int lane = tid & 31, wid = tid >> 5;
    #pragma unroll
    for (int o = 16; o; o >>= 1) {
        s  += __shfl_down_sync(0xffffffffu, s, o);
        ss += __shfl_down_sync(0xffffffffu, ss, o);
    }
    if (lane == 0) { rs[wid] = s; rss[wid] = ss; }
    if (tid < 32) { ws[tid] = w[g * 32 + tid]; bs[tid] = bv[g * 32 + tid]; }
    __syncthreads();
    if (wid == 0) {
        s  = (lane < 16) ? rs[lane]  : 0.f;
        ss = (lane < 16) ? rss[lane] : 0.f;
        #pragma unroll
        for (int o = 8; o; o >>= 1) {
            s  += __shfl_down_sync(0xffffffffu, s, o);
            ss += __shfl_down_sync(0xffffffffu, ss, o);
        }
        if (lane == 0) { rs[0] = s; rss[0] = ss; }
    }
    __syncthreads();
    float mean = rs[0] / (float)NEL;
    float var  = rss[0] / (float)NEL - mean * mean;
    float rstd = rsqrtf(var + 1e-5f);

    __half* out = g_xnh + (size_t)b * HWn * Cc + g * 32;
    int c  = tid >> 4, pl = (tid & 15) * 8;
    int pl2 = tid >> 2, c8 = (tid & 3) * 8;

    for (int p0 = 0; p0 < HWn; p0 += 128) {
        float4 v0 = *(const float4*)(xb + (size_t)c * HWn + p0 + pl);
        float4 v1 = *(const float4*)(xb + (size_t)c * HWn + p0 + pl + 4);
        __syncthreads();
        *(float4*)&sm[c][pl]     = v0;
        *(float4*)&sm[c][pl + 4] = v1;
        __syncthreads();
        __half2 h[4];
        #pragma unroll
        for (int jj = 0; jj < 4; jj++) {
            int c0 = c8 + jj * 2;
            float a0 = (sm[c0][pl2]     - mean) * rstd * ws[c0]     + bs[c0];
            float a1 = (sm[c0 + 1][pl2] - mean) * rstd * ws[c0 + 1] + bs[c0 + 1];
            h[jj] = __floats2half2_rn(a0, a1);
        }
        *(uint4*)&out[(size_t)(p0 + pl2) * Cc + c8] = *(uint4*)h;
    }
}

// ---------------- fp16 NT GEMM core ----------------------------------------------
__device__ __forceinline__ void gemm16(const __half* __restrict__ Ag,
                                       const __half* __restrict__ Bg,
                                       __half* gsm, float acc[2][8][4]) {
    int t = threadIdx.x;
    #pragma unroll
    for (int i = 0; i < 16; i++) {
        int idx = t + 256 * i;
        int row = idx >> 5, pc = idx & 31;
        cp16(gsm + row * GP + pc * 8, Ag + (size_t)row * 256 + pc * 8);
        cp16(gsm + 128 * GP + row * GP + pc * 8, Bg + (size_t)row * 256 + pc * 8);
    }
    cpcommit();
    cpwait<0>();
    __syncthreads();

    int wid = t >> 5, lane = t & 31;
    int wm = (wid >> 1) * 32, wn = (wid & 1) * 64;
    uint32_t sb = (uint32_t)__cvta_generic_to_shared(gsm);
    uint32_t aA = sb + (uint32_t)((wm + (lane & 15)) * GP + (lane >> 4) * 8) * 2;
    uint32_t rowKV = (uint32_t)(((lane >> 4) << 3) + (lane & 7));
    uint32_t colHi = (uint32_t)(((lane >> 3) & 1) << 3);
    uint32_t aB = sb + (uint32_t)(128 * GP + (wn + rowKV) * GP + colHi) * 2;

    #pragma unroll
    for (int ks = 0; ks < 16; ks++) {
        uint32_t a[2][4];
        ldsm4(a[0][0], a[0][1], a[0][2], a[0][3], aA + ks * 32);
        ldsm4(a[1][0], a[1][1], a[1][2], a[1][3], aA + 16 * GP * 2 + ks * 32);
        #pragma unroll
        for (int ng = 0; ng < 4; ng++) {
            uint32_t b0, b1, b2, b3;
            ldsm4(b0, b1, b2, b3, aB + ng * (16 * GP * 2) + ks * 32);
            #pragma unroll
            for (int mt = 0; mt < 2; mt++) {
                mma16(acc[mt][ng * 2],     a[mt][0], a[mt][1], a[mt][2], a[mt][3], b0, b1);
                mma16(acc[mt][ng * 2 + 1], a[mt][0], a[mt][1], a[mt][2], a[mt][3], b2, b3);
            }
        }
    }
}

// ---------------- QKV GEMM ---------------------------------------------------------
__global__ __launch_bounds__(256) void qkv_kernel(const float* __restrict__ bias) {
    extern __shared__ __align__(16) __half gsm[];
    int b = blockIdx.z;
    int pm = blockIdx.y * 128;
    int on = blockIdx.x * 128;
    const __half* Ag = g_xnh + (size_t)b * HWn * Cc + (size_t)pm * Cc;
    const __half* Bg = g_qwh + (size_t)on * Cc;

    float acc[2][8][4] = {};
    gemm16(Ag, Bg, gsm, acc);

    int t = threadIdx.x, wid = t >> 5, lane = t & 31, g = lane >> 2, t4 = lane & 3;
    int wm = (wid >> 1) * 32, wn = (wid & 1) * 64;

    if (on < 512) {
        __half* dst = ((on < 256) ? g_q : g_k) + (size_t)b * HWn * Cc;
        int obase = on & 255;
        #pragma unroll
        for (int nt = 0; nt < 8; nt++) {
            int ocol = wn + nt * 8 + t4 * 2;
            float2 bb = *(const float2*)&bias[on + ocol];
            #pragma unroll
            for (int mt = 0; mt < 2; mt++) {
                int p0 = pm + wm + mt * 16 + g;
                __half2 v0 = __floats2half2_rn(acc[mt][nt][0] + bb.x, acc[mt][nt][1] + bb.y);
                __half2 v1 = __floats2half2_rn(acc[mt][nt][2] + bb.x, acc[mt][nt][3] + bb.y);
                *(__half2*)&dst[(size_t)p0 * Cc + obase + ocol]       = v0;
                *(__half2*)&dst[(size_t)(p0 + 8) * Cc + obase + ocol] = v1;
            }
        }
    } else {
        __half* dst = g_vt + (size_t)b * Cc * HWn;
        #pragma unroll
        for (int nt = 0; nt < 8; nt++) {
            int ocol = wn + nt * 8 + t4 * 2;
            int c0 = (on - 512) + ocol;
            float2 bb = *(const float2*)&bias[on + ocol];
            #pragma unroll
            for (int mt = 0; mt < 2; mt++) {
                int p0 = pm + wm + mt * 16 + g;
                dst[(size_t)c0 * HWn + p0]           = __float2half(acc[mt][nt][0] + bb.x);
                dst[(size_t)(c0 + 1) * HWn + p0]     = __float2half(acc[mt][nt][1] + bb.y);
                dst[(size_t)c0 * HWn + p0 + 8]       = __float2half(acc[mt][nt][2] + bb.x);
                dst[(size_t)(c0 + 1) * HWn + p0 + 8] = __float2half(acc[mt][nt][3] + bb.y);
            }
        }
    }
}

// ---------------- flash: warp-specialized, split-KV (m-half per CTA) -------------
__device__ __forceinline__ void copyK16(const __half* Kg, int kt, __half* kb, int t) {
    #pragma unroll
    for (int i = 0; i < 8; i++) {
        int idx = t + 256 * i;
        int row = idx >> 5, pc = idx & 31;
        cp16(kb + row * QPH + pc * 8, Kg + (size_t)(kt * 64 + row) * Cc + pc * 8);
    }
}
__device__ __forceinline__ void copyV16(const __half* Vtg, int kt, __half* vb, int t) {
    #pragma unroll
    for (int i = 0; i < 8; i++) {
        int idx = t + 256 * i;
        int c = idx >> 3, pc = idx & 7;
        cp16(vb + c * VPH + pc * 8, Vtg + (size_t)c * HWn + kt * 64 + pc * 8);
    }
}

__global__ void __launch_bounds__(512, 1) flash_kernel() {
    extern __shared__ __align__(16) __half smh[];
    float* smf = (float*)(smh + OFF_F);
    int b = blockIdx.y;
    int half = blockIdx.z;          // key-range half: [half*2048, half*2048+2048)
    int qbase = blockIdx.x * 64;
    const int NIT = 32;
    int ktbase = half * NIT;
    const __half* Qg  = g_q  + (size_t)b * HWn * Cc + (size_t)qbase * Cc;
    const __half* Kg  = g_k  + (size_t)b * HWn * Cc;
    const __half* Vtg = g_vt + (size_t)b * Cc * HWn;

    int t = threadIdx.x;
    int wid = t >> 5, lane = t & 31, g = lane >> 2, t4 = lane & 3;
    bool isProd = (wid < 8);
    uint32_t sb = (uint32_t)__cvta_generic_to_shared(smh);
    uint32_t rowKV = (uint32_t)(((lane >> 4) << 3) + (lane & 7));
    uint32_t colHi = (uint32_t)(((lane >> 3) & 1) << 3);

    int mi = (wid & 7) >> 1, ni = wid & 1;
    int wm = mi * 16;
    int r0 = wm + g, r1 = r0 + 8;
    uint32_t aQ  = sb + (uint32_t)(OFF_Q  + (wm + (lane & 15)) * QPH + (lane >> 4) * 8) * 2;
    uint32_t aK0 = sb + (uint32_t)(OFF_K0 + (ni * 32 + rowKV) * QPH + colHi) * 2;
    uint32_t aK1 = sb + (uint32_t)(OFF_K1 + (ni * 32 + rowKV) * QPH + colHi) * 2;

    int cw = wid - 8;
    int cq = (cw > 0 ? cw : 0) >> 1, cc = cw & 1;
    int cr0 = cq * 16 + g, cr1 = cr0 + 8;
    uint32_t aP0 = sb + (uint32_t)(OFF_P0 + (cq * 16 + (lane & 15)) * PPH + (lane >> 4) * 8) * 2;
    uint32_t aP1 = sb + (uint32_t)(OFF_P1 + (cq * 16 + (lane & 15)) * PPH + (lane >> 4) * 8) * 2;
    uint32_t aV0 = sb + (uint32_t)(OFF_V0 + (cc * 128 + rowKV) * VPH + colHi) * 2;
    uint32_t aV1 = sb + (uint32_t)(OFF_V1 + (cc * 128 + rowKV) * VPH + colHi) * 2;

    float oacc[16][4] = {};
    float M0 = -1e30f, M1 = -1e30f, L0 = 0.f, L1 = 0.f;

    if (isProd) copyK16(Kg, ktbase, smh + OFF_K0, t);
    else        copyK16(Qg, 0, smh + OFF_Q, t - 256);
    cpcommit();
    cpwait<0>();
    __syncthreads();

    const float SCL = 0.09016844f;   // log2(e)/16

    for (int i = 0; i <= NIT; i++) {
        if (isProd) {
            if (i < NIT - 1) {
                copyK16(Kg, ktbase + i + 1, smh + (((i + 1) & 1) ? OFF_K1 : OFF_K0), t);
                cpcommit();
            }
            if (i < NIT) {
                uint32_t kb = (i & 1) ? aK1 : aK0;
                float sacc[4][4] = {};
                #pragma unroll
                for (int ks = 0; ks < 16; ks++) {
                    uint32_t q0, q1, q2, q3;
                    ldsm4(q0, q1, q2, q3, aQ + ks * 32);
                    #pragma unroll
                    for (int ntp = 0; ntp < 2; ntp++) {
                        uint32_t b0, b1, b2, b3;
                        ldsm4(b0, b1, b2, b3, kb + ntp * (16 * QPH * 2) + ks * 32);
                        mma16(sacc[ntp * 2],     q0, q1, q2, q3, b0, b1);
                        mma16(sacc[ntp * 2 + 1], q0, q1, q2, q3, b2, b3);
                    }
                }
                float mx0 = -1e30f, mx1 = -1e30f;
                #pragma unroll
                for (int nt = 0; nt < 4; nt++) {
                    #pragma unroll
                    for (int jj = 0; jj < 4; jj++) sacc[nt][jj] *= SCL;
                    mx0 = fmaxf(mx0, fmaxf(sacc[nt][0], sacc[nt][1]));
                    mx1 = fmaxf(mx1, fmaxf(sacc[nt][2], sacc[nt][3]));
                }
                mx0 = fmaxf(mx0, __shfl_xor_sync(0xffffffffu, mx0, 1));
                mx0 = fmaxf(mx0, __shfl_xor_sync(0xffffffffu, mx0, 2));
                mx1 = fmaxf(mx1, __shfl_xor_sync(0xffffffffu, mx1, 1));
                mx1 = fmaxf(mx1, __shfl_xor_sync(0xffffffffu, mx1, 2));
                if (t4 == 0) {
                    smf[F_MX + ni * 64 + r0] = mx0;
                    smf[F_MX + ni * 64 + r1] = mx1;
                }
                asm volatile("bar.sync 1, 256;" ::: "memory");
                float Mn0 = fmaxf(M0, fmaxf(mx0, smf[F_MX + (1 - ni) * 64 + r0]));
                float Mn1 = fmaxf(M1, fmaxf(mx1, smf[F_MX + (1 - ni) * 64 + r1]));
                float f0 = exp2f(M0 - Mn0), f1 = exp2f(M1 - Mn1);
                M0 = Mn0; M1 = Mn1;
                if (ni == 0 && t4 == 0) {
                    smf[(i & 1) * 64 + r0] = f0;
                    smf[(i & 1) * 64 + r1] = f1;
                }
                float s0 = 0.f, s1 = 0.f;
                __half* Pb = smh + ((i & 1) ? OFF_P1 : OFF_P0);
                #pragma unroll
                for (int nt = 0; nt < 4; nt++) {
                    float p00 = exp2f(sacc[nt][0] - Mn0);
                    float p01 = exp2f(sacc[nt][1] - Mn0);
                    float p10 = exp2f(sacc[nt][2] - Mn1);
                    float p11 = exp2f(sacc[nt][3] - Mn1);
                    s0 += p00 + p01; s1 += p10 + p11;
                    __half2 u0 = __floats2half2_rn(p00, p01);
                    __half2 u1 = __floats2half2_rn(p10, p11);
                    int ccol = ni * 32 + nt * 8 + t4 * 2;
                    *(__half2*)&Pb[r0 * PPH + ccol] = u0;
                    *(__half2*)&Pb[r1 * PPH + ccol] = u1;
                }
                s0 += __shfl_xor_sync(0xffffffffu, s0, 1);
                s0 += __shfl_xor_sync(0xffffffffu, s0, 2);
                s1 += __shfl_xor_sync(0xffffffffu, s1, 1);
                s1 += __shfl_xor_sync(0xffffffffu, s1, 2);
                L0 = L0 * f0 + s0;
                L1 = L1 * f1 + s1;
            } else {
                // i == NIT: publish L halves and running M (same across ni)
                if (t4 == 0) {
                    smf[F_LS + ni * 64 + r0] = L0;
                    smf[F_LS + ni * 64 + r1] = L1;
                    if (ni == 0) {
                        smf[F_MX + r0] = M0;
                        smf[F_MX + r1] = M1;
                    }
                }
            }
        } else {
            if (i < NIT) {
                copyV16(Vtg, ktbase + i, smh + ((i & 1) ? OFF_V1 : OFF_V0), t - 256);
                cpcommit();
            }
            if (i >= 1) {
                int j = i - 1;
                float f0 = smf[(j & 1) * 64 + cr0];
                float f1 = smf[(j & 1) * 64 + cr1];
                bool nor = (f0 == 1.f) && (f1 == 1.f);
                if (__ballot_sync(0xffffffffu, nor) != 0xffffffffu) {
                    #pragma unroll
                    for (int q = 0; q < 16; q++) {
                        oacc[q][0] *= f0; oacc[q][1] *= f0;
                        oacc[q][2] *= f1; oacc[q][3] *= f1;
                    }
                }
                uint32_t aP = (j & 1) ? aP1 : aP0;
                uint32_t aV = (j & 1) ? aV1 : aV0;
                #pragma unroll
                for (int km = 0; km < 4; km++) {
                    uint32_t pa0, pa1, pa2, pa3;
                    ldsm4(pa0, pa1, pa2, pa3, aP + km * 32);
                    #pragma unroll
                    for (int ct = 0; ct < 8; ct++) {
                        uint32_t v0, v1, v2, v3;
                        ldsm4(v0, v1, v2, v3, aV + ct * (16 * VPH * 2) + km * 32);
                        mma16(oacc[ct * 2],     pa0, pa1, pa2, pa3, v0, v1);
                        mma16(oacc[ct * 2 + 1], pa0, pa1, pa2, pa3, v2, v3);
                    }
                }
            }
        }
        cpwait<0>();
        __syncthreads();
    }

    // epilogue: consumers write UNNORMALIZED fp32 partials + per-row (M, L)
    if (!isProd) {
        float Lt0 = smf[F_LS + cr0] + smf[F_LS + 64 + cr0];
        float Lt1 = smf[F_LS + cr1] + smf[F_LS + 64 + cr1];
        float Mv0 = smf[F_MX + cr0];
        float Mv1 = smf[F_MX + cr1];
        float* OP = g_op + ((size_t)(half * Bn + b) * HWn + qbase) * Cc;
        #pragma unroll
        for (int q = 0; q < 16; q++) {
            int ch = cc * 128 + q * 8 + t4 * 2;
            *(float2*)&OP[(size_t)cr0 * Cc + ch] = make_float2(oacc[q][0], oacc[q][1]);
            *(float2*)&OP[(size_t)cr1 * Cc + ch] = make_float2(oacc[q][2], oacc[q][3]);
        }
        if (cc == 0 && t4 == 0) {
            size_t mlbase = (size_t)(half * Bn + b) * HWn + qbase;
            g_ml[mlbase + cr0] = make_float2(Mv0, Lt0);
            g_ml[mlbase + cr1] = make_float2(Mv1, Lt1);
        }
    }
}

// ---------------- merge: combine the two KV halves (log-sum-exp) -----------------
__global__ __launch_bounds__(256) void merge_kernel() {
    int row = blockIdx.x * 4 + (threadIdx.x >> 6);       // [0, Bn*HWn)
    int ch  = (threadIdx.x & 63) * 4;
    const size_t HALF = (size_t)Bn * HWn;

    float2 ml0 = g_ml[row];
    float2 ml1 = g_ml[HALF + row];
    float M = fmaxf(ml0.x, ml1.x);
    float w0 = exp2f(ml0.x - M), w1 = exp2f(ml1.x - M);
    float inv = 1.0f / (w0 * ml0.y + w1 * ml1.y);

    float4 o0 = *(const float4*)&g_op[(size_t)row * Cc + ch];
    float4 o1 = *(const float4*)&g_op[(HALF + row) * Cc + ch];
    __half2 h0 = __floats2half2_rn((w0 * o0.x + w1 * o1.x) * inv,
                                   (w0 * o0.y + w1 * o1.y) * inv);
    __half2 h1 = __floats2half2_rn((w0 * o0.z + w1 * o1.z) * inv,
                                   (w0 * o0.w + w1 * o1.w) * inv);
    uint2 pk = { H2U(h0), H2U(h1) };
    *(uint2*)&g_aoh[(size_t)row * Cc + ch] = pk;
}

// ---------------- proj GEMM (fp16) + residual ------------------------------------
__global__ __launch_bounds__(256) void proj_kernel(const float* __restrict__ x,
                                                   const float* __restrict__ pb,
                                                   float* __restrict__ out) {
    extern __shared__ __align__(16) __half gsm[];
    int b = blockIdx.z;
    int om = blockIdx.y * 128;
    int pn = blockIdx.x * 128;
    const __half* Ag = g_pwh + (size_t)om * Cc;
    const __half* Bg = g_aoh + (size_t)b * HWn * Cc + (size_t)pn * Cc;

    float acc[2][8][4] = {};
    gemm16(Ag, Bg, gsm, acc);

    int t = threadIdx.x, wid = t >> 5, lane = t & 31, g = lane >> 2, t4 = lane & 3;
    int wm = (wid >> 1) * 32, wn = (wid & 1) * 64;

    #pragma unroll
    for (int mt = 0; mt < 2; mt++) {
        int o0 = om + wm + mt * 16 + g;
        float b0 = pb[o0], b1 = pb[o0 + 8];
        #pragma unroll
        for (int nt = 0; nt < 8; nt++) {
            int p0 = pn + wn + nt * 8 + t4 * 2;
            size_t off0 = ((size_t)b * Cc + o0) * HWn + p0;
            size_t off1 = ((size_t)b * Cc + o0 + 8) * HWn + p0;
            float2 x0 = *(const float2*)&x[off0];
            float2 x1 = *(const float2*)&x[off1];
            float2 v0 = { acc[mt][nt][0] + b0 + x0.x, acc[mt][nt][1] + b0 + x0.y };
            float2 v1 = { acc[mt][nt][2] + b1 + x1.x, acc[mt][nt][3] + b1 + x1.y };
            *(float2*)&out[off0] = v0;
            *(float2*)&out[off1] = v1;
        }
    }
}

// ---------------- launch ---------------------------------------------------------
extern "C" void kernel_launch(void* const* d_in, const int* in_sizes, int n_in,
                              void* d_out, int out_size) {
    const float* x  = (const float*)d_in[0];
    const float* nw = (const float*)d_in[1];
    const float* nb = (const float*)d_in[2];
    const float* qw = (const float*)d_in[3];
    const float* qb = (const float*)d_in[4];
    const float* pw = (const float*)d_in[5];
    const float* pb = (const float*)d_in[6];
    float* out = (float*)d_out;

    cudaFuncSetAttribute(flash_kernel, cudaFuncAttributeMaxDynamicSharedMemorySize,
                         SMEM_BYTES);
    cudaFuncSetAttribute(qkv_kernel, cudaFuncAttributeMaxDynamicSharedMemorySize,
                         GEMM_SMEM);
    cudaFuncSetAttribute(proj_kernel, cudaFuncAttributeMaxDynamicSharedMemorySize,
                         GEMM_SMEM);

    gn_kernel<<<64 + 384, 512>>>(x, nw, nb, qw, pw);
    qkv_kernel<<<dim3(6, 32, 8), 256, GEMM_SMEM>>>(qb);
    flash_kernel<<<dim3(64, 8, 2), 512, SMEM_BYTES>>>();
    merge_kernel<<<Bn * HWn / 4, 256>>>();
    proj_kernel<<<dim3(32, 2, 8), 256, GEMM_SMEM>>>(x, pb, out);
}

// round 14
// speedup vs baseline: 1.1139x; 1.0262x over previous
#include <cuda_runtime.h>
#include <cuda_fp16.h>
#include <cstdint>

#define Bn  8
#define Cc  256
#define HWn 4096

// ---- flash smem layout (half offsets) ----
#define QPH 264
#define VPH 72
#define PPH 72
#define OFF_Q  0
#define OFF_K0 16896
#define OFF_K1 33792
#define OFF_V0 50688
#define OFF_V1 69120
#define OFF_P0 87552
#define OFF_P1 92160
#define OFF_F  96768
#define F_MX 128
#define F_LS 256
#define SMEM_BYTES (OFF_F * 2 + 384 * 4)   // 195072 B

// ---- fp16 GEMM tiles (qkv/proj) ----
#define GP 264
#define GEMM_SMEM (2 * 128 * GP * 2)       // 135168 B

// ---------------- scratch -----------------------------------------------------
__device__ __half g_xnh[(size_t)Bn * HWn * Cc];
__device__ __half g_qwh[768 * 256];
__device__ __half g_pwh[256 * 256];
__device__ __half g_q [(size_t)Bn * HWn * Cc];
__device__ __half g_k [(size_t)Bn * HWn * Cc];
__device__ __half g_vt[(size_t)Bn * Cc * HWn];
__device__ __half g_aoh[(size_t)Bn * HWn * Cc];
__device__ float  g_op [(size_t)2 * Bn * HWn * Cc];   // partial O (2 halves), fp32
__device__ float2 g_ml [(size_t)2 * Bn * HWn];        // per-row (M, L) per half
__device__ float2 g_mr [64];                          // per-(b,g) mean/rstd

// ---------------- helpers ------------------------------------------------------
__device__ __forceinline__ void mma16(float c[4], uint32_t a0, uint32_t a1, uint32_t a2,
                                      uint32_t a3, uint32_t b0, uint32_t b1) {
    asm("mma.sync.aligned.m16n8k16.row.col.f32.f16.f16.f32 "
        "{%0,%1,%2,%3},{%4,%5,%6,%7},{%8,%9},{%0,%1,%2,%3};"
        : "+f"(c[0]), "+f"(c[1]), "+f"(c[2]), "+f"(c[3])
        : "r"(a0), "r"(a1), "r"(a2), "r"(a3), "r"(b0), "r"(b1));
}
__device__ __forceinline__ void ldsm4(uint32_t& r0, uint32_t& r1, uint32_t& r2,
                                      uint32_t& r3, uint32_t a) {
    asm volatile("ldmatrix.sync.aligned.m8n8.x4.shared.b16 {%0,%1,%2,%3}, [%4];"
        : "=r"(r0), "=r"(r1), "=r"(r2), "=r"(r3) : "r"(a));
}
#define H2U(x) (*(const uint32_t*)&(x))

__device__ __forceinline__ void cp16(void* dst, const void* src) {
    uint32_t d = (uint32_t)__cvta_generic_to_shared(dst);
    asm volatile("cp.async.cg.shared.global [%0], [%1], 16;\n" :: "r"(d), "l"(src));
}
__device__ __forceinline__ void cpcommit() { asm volatile("cp.async.commit_group;\n"); }
template<int N> __device__ __forceinline__ void cpwait() {
    asm volatile("cp.async.wait_group %0;\n" :: "n"(N));
}

// ---------------- GN stats (64 blocks) + fused weight conversion (192 blocks) ----
__global__ __launch_bounds__(1024) void gn_stats(const float* __restrict__ x,
                                                 const float* __restrict__ qw,
                                                 const float* __restrict__ pw) {
    if (blockIdx.x >= 64) {
        int i = (blockIdx.x - 64) * 1024 + threadIdx.x;   // 192*1024 = 768*256 exactly
        g_qwh[i] = __float2half(qw[i]);
        if (i < 256 * 256) g_pwh[i] = __float2half(pw[i]);
        return;
    }
    int b = blockIdx.x >> 3, g = blockIdx.x & 7;
    const float4* xb = (const float4*)(x + ((size_t)b * Cc + (size_t)g * 32) * HWn);
    const int N4 = 32 * HWn / 4;   // 32768

    float s = 0.f, ss = 0.f;
    for (int i = threadIdx.x; i < N4; i += 1024) {
        float4 v = xb[i];
        s  += v.x + v.y + v.z + v.w;
        ss += v.x * v.x + v.y * v.y + v.z * v.z + v.w * v.w;
    }
    __shared__ float rs[32], rss[32];
    int lane = threadIdx.x & 31, wid = threadIdx.x >> 5;
    #pragma unroll
    for (int o = 16; o; o >>= 1) {
        s  += __shfl_down_sync(0xffffffffu, s, o);
        ss += __shfl_down_sync(0xffffffffu, ss, o);
    }
    if (lane == 0) { rs[wid] = s; rss[wid] = ss; }
    __syncthreads();
    if (wid == 0) {
        s  = rs[lane];
        ss = rss[lane];
        #pragma unroll
        for (int o = 16; o; o >>= 1) {
            s  += __shfl_down_sync(0xffffffffu, s, o);
            ss += __shfl_down_sync(0xffffffffu, ss, o);
        }
        if (lane == 0) {
            const float NEL = 32.0f * HWn;
            float mean = s / NEL;
            float var  = ss / NEL - mean * mean;
            g_mr[blockIdx.x] = make_float2(mean, rsqrtf(var + 1e-5f));
        }
    }
}

// ---------------- GN apply (512 blocks, smem transpose, fp16 token-major) --------
__global__ __launch_bounds__(512) void gn_apply(const float* __restrict__ x,
                                                const float* __restrict__ w,
                                                const float* __restrict__ bv) {
    __shared__ float sm[32][132];
    __shared__ float ws[32], bs[32];
    int bg = blockIdx.x >> 3, slice = blockIdx.x & 7;
    int b = bg >> 3, g = bg & 7;
    const float* xb = x + ((size_t)b * Cc + (size_t)g * 32) * HWn;
    int tid = threadIdx.x;
    float2 mr = g_mr[bg];
    float mean = mr.x, rstd = mr.y;
    if (tid < 32) { ws[tid] = w[g * 32 + tid]; bs[tid] = bv[g * 32 + tid]; }

    __half* out = g_xnh + (size_t)b * HWn * Cc + g * 32;
    int c  = tid >> 4, pl = (tid & 15) * 8;
    int pl2 = tid >> 2, c8 = (tid & 3) * 8;
    int pbase = slice * 512;

    for (int p0 = pbase; p0 < pbase + 512; p0 += 128) {
        float4 v0 = *(const float4*)(xb + (size_t)c * HWn + p0 + pl);
        float4 v1 = *(const float4*)(xb + (size_t)c * HWn + p0 + pl + 4);
        __syncthreads();
        *(float4*)&sm[c][pl]     = v0;
        *(float4*)&sm[c][pl + 4] = v1;
        __syncthreads();
        __half2 h[4];
        #pragma unroll
        for (int jj = 0; jj < 4; jj++) {
            int c0 = c8 + jj * 2;
            float a0 = (sm[c0][pl2]     - mean) * rstd * ws[c0]     + bs[c0];
            float a1 = (sm[c0 + 1][pl2] - mean) * rstd * ws[c0 + 1] + bs[c0 + 1];
            h[jj] = __floats2half2_rn(a0, a1);
        }
        *(uint4*)&out[(size_t)(p0 + pl2) * Cc + c8] = *(uint4*)h;
    }
}

// ---------------- fp16 NT GEMM core ----------------------------------------------
__device__ __forceinline__ void gemm16(const __half* __restrict__ Ag,
                                       const __half* __restrict__ Bg,
                                       __half* gsm, float acc[2][8][4]) {
    int t = threadIdx.x;
    #pragma unroll
    for (int i = 0; i < 16; i++) {
        int idx = t + 256 * i;
        int row = idx >> 5, pc = idx & 31;
        cp16(gsm + row * GP + pc * 8, Ag + (size_t)row * 256 + pc * 8);
        cp16(gsm + 128 * GP + row * GP + pc * 8, Bg + (size_t)row * 256 + pc * 8);
    }
    cpcommit();
    cpwait<0>();
    __syncthreads();

    int wid = t >> 5, lane = t & 31;
    int wm = (wid >> 1) * 32, wn = (wid & 1) * 64;
    uint32_t sb = (uint32_t)__cvta_generic_to_shared(gsm);
    uint32_t aA = sb + (uint32_t)((wm + (lane & 15)) * GP + (lane >> 4) * 8) * 2;
    uint32_t rowKV = (uint32_t)(((lane >> 4) << 3) + (lane & 7));
    uint32_t colHi = (uint32_t)(((lane >> 3) & 1) << 3);
    uint32_t aB = sb + (uint32_t)(128 * GP + (wn + rowKV) * GP + colHi) * 2;

    #pragma unroll
    for (int ks = 0; ks < 16; ks++) {
        uint32_t a[2][4];
        ldsm4(a[0][0], a[0][1], a[0][2], a[0][3], aA + ks * 32);
        ldsm4(a[1][0], a[1][1], a[1][2], a[1][3], aA + 16 * GP * 2 + ks * 32);
        #pragma unroll
        for (int ng = 0; ng < 4; ng++) {
            uint32_t b0, b1, b2, b3;
            ldsm4(b0, b1, b2, b3, aB + ng * (16 * GP * 2) + ks * 32);
            #pragma unroll
            for (int mt = 0; mt < 2; mt++) {
                mma16(acc[mt][ng * 2],     a[mt][0], a[mt][1], a[mt][2], a[mt][3], b0, b1);
                mma16(acc[mt][ng * 2 + 1], a[mt][0], a[mt][1], a[mt][2], a[mt][3], b2, b3);
            }
        }
    }
}

// ---------------- QKV GEMM ---------------------------------------------------------
__global__ __launch_bounds__(256) void qkv_kernel(const float* __restrict__ bias) {
    extern __shared__ __align__(16) __half gsm[];
    int b = blockIdx.z;
    int pm = blockIdx.y * 128;
    int on = blockIdx.x * 128;
    const __half* Ag = g_xnh + (size_t)b * HWn * Cc + (size_t)pm * Cc;
    const __half* Bg = g_qwh + (size_t)on * Cc;

    float acc[2][8][4] = {};
    gemm16(Ag, Bg, gsm, acc);

    int t = threadIdx.x, wid = t >> 5, lane = t & 31, g = lane >> 2, t4 = lane & 3;
    int wm = (wid >> 1) * 32, wn = (wid & 1) * 64;

    if (on < 512) {
        __half* dst = ((on < 256) ? g_q : g_k) + (size_t)b * HWn * Cc;
        int obase = on & 255;
        #pragma unroll
        for (int nt = 0; nt < 8; nt++) {
            int ocol = wn + nt * 8 + t4 * 2;
            float2 bb = *(const float2*)&bias[on + ocol];
            #pragma unroll
            for (int mt = 0; mt < 2; mt++) {
                int p0 = pm + wm + mt * 16 + g;
                __half2 v0 = __floats2half2_rn(acc[mt][nt][0] + bb.x, acc[mt][nt][1] + bb.y);
                __half2 v1 = __floats2half2_rn(acc[mt][nt][2] + bb.x, acc[mt][nt][3] + bb.y);
                *(__half2*)&dst[(size_t)p0 * Cc + obase + ocol]       = v0;
                *(__half2*)&dst[(size_t)(p0 + 8) * Cc + obase + ocol] = v1;
            }
        }
    } else {
        __half* dst = g_vt + (size_t)b * Cc * HWn;
        #pragma unroll
        for (int nt = 0; nt < 8; nt++) {
            int ocol = wn + nt * 8 + t4 * 2;
            int c0 = (on - 512) + ocol;
            float2 bb = *(const float2*)&bias[on + ocol];
            #pragma unroll
            for (int mt = 0; mt < 2; mt++) {
                int p0 = pm + wm + mt * 16 + g;
                dst[(size_t)c0 * HWn + p0]           = __float2half(acc[mt][nt][0] + bb.x);
                dst[(size_t)(c0 + 1) * HWn + p0]     = __float2half(acc[mt][nt][1] + bb.y);
                dst[(size_t)c0 * HWn + p0 + 8]       = __float2half(acc[mt][nt][2] + bb.x);
                dst[(size_t)(c0 + 1) * HWn + p0 + 8] = __float2half(acc[mt][nt][3] + bb.y);
            }
        }
    }
}

// ---------------- flash: warp-specialized, split-KV (m-half per CTA) -------------
__device__ __forceinline__ void copyK16(const __half* Kg, int kt, __half* kb, int t) {
    #pragma unroll
    for (int i = 0; i < 8; i++) {
        int idx = t + 256 * i;
        int row = idx >> 5, pc = idx & 31;
        cp16(kb + row * QPH + pc * 8, Kg + (size_t)(kt * 64 + row) * Cc + pc * 8);
    }
}
__device__ __forceinline__ void copyV16(const __half* Vtg, int kt, __half* vb, int t) {
    #pragma unroll
    for (int i = 0; i < 8; i++) {
        int idx = t + 256 * i;
        int c = idx >> 3, pc = idx & 7;
        cp16(vb + c * VPH + pc * 8, Vtg + (size_t)c * HWn + kt * 64 + pc * 8);
    }
}

__global__ void __launch_bounds__(512, 1) flash_kernel() {
    extern __shared__ __align__(16) __half smh[];
    float* smf = (float*)(smh + OFF_F);
    int b = blockIdx.y;
    int half = blockIdx.z;          // key-range half: [half*2048, half*2048+2048)
    int qbase = blockIdx.x * 64;
    const int NIT = 32;
    int ktbase = half * NIT;
    const __half* Qg  = g_q  + (size_t)b * HWn * Cc + (size_t)qbase * Cc;
    const __half* Kg  = g_k  + (size_t)b * HWn * Cc;
    const __half* Vtg = g_vt + (size_t)b * Cc * HWn;

    int t = threadIdx.x;
    int wid = t >> 5, lane = t & 31, g = lane >> 2, t4 = lane & 3;
    bool isProd = (wid < 8);
    uint32_t sb = (uint32_t)__cvta_generic_to_shared(smh);
    uint32_t rowKV = (uint32_t)(((lane >> 4) << 3) + (lane & 7));
    uint32_t colHi = (uint32_t)(((lane >> 3) & 1) << 3);

    int mi = (wid & 7) >> 1, ni = wid & 1;
    int wm = mi * 16;
    int r0 = wm + g, r1 = r0 + 8;
    uint32_t aQ  = sb + (uint32_t)(OFF_Q  + (wm + (lane & 15)) * QPH + (lane >> 4) * 8) * 2;
    uint32_t aK0 = sb + (uint32_t)(OFF_K0 + (ni * 32 + rowKV) * QPH + colHi) * 2;
    uint32_t aK1 = sb + (uint32_t)(OFF_K1 + (ni * 32 + rowKV) * QPH + colHi) * 2;

    int cw = wid - 8;
    int cq = (cw > 0 ? cw : 0) >> 1, cc = cw & 1;
    int cr0 = cq * 16 + g, cr1 = cr0 + 8;
    uint32_t aP0 = sb + (uint32_t)(OFF_P0 + (cq * 16 + (lane & 15)) * PPH + (lane >> 4) * 8) * 2;
    uint32_t aP1 = sb + (uint32_t)(OFF_P1 + (cq * 16 + (lane & 15)) * PPH + (lane >> 4) * 8) * 2;
    uint32_t aV0 = sb + (uint32_t)(OFF_V0 + (cc * 128 + rowKV) * VPH + colHi) * 2;
    uint32_t aV1 = sb + (uint32_t)(OFF_V1 + (cc * 128 + rowKV) * VPH + colHi) * 2;

    float oacc[16][4] = {};
    float M0 = -1e30f, M1 = -1e30f, L0 = 0.f, L1 = 0.f;

    if (isProd) copyK16(Kg, ktbase, smh + OFF_K0, t);
    else        copyK16(Qg, 0, smh + OFF_Q, t - 256);
    cpcommit();
    cpwait<0>();
    __syncthreads();

    const float SCL = 0.09016844f;   // log2(e)/16

    for (int i = 0; i <= NIT; i++) {
        if (isProd) {
            if (i < NIT - 1) {
                copyK16(Kg, ktbase + i + 1, smh + (((i + 1) & 1) ? OFF_K1 : OFF_K0), t);
                cpcommit();
            }
            if (i < NIT) {
                uint32_t kb = (i & 1) ? aK1 : aK0;
                float sacc[4][4] = {};
                #pragma unroll
                for (int ks = 0; ks < 16; ks++) {
                    uint32_t q0, q1, q2, q3;
                    ldsm4(q0, q1, q2, q3, aQ + ks * 32);
                    #pragma unroll
                    for (int ntp = 0; ntp < 2; ntp++) {
                        uint32_t b0, b1, b2, b3;
                        ldsm4(b0, b1, b2, b3, kb + ntp * (16 * QPH * 2) + ks * 32);
                        mma16(sacc[ntp * 2],     q0, q1, q2, q3, b0, b1);
                        mma16(sacc[ntp * 2 + 1], q0, q1, q2, q3, b2, b3);
                    }
                }
                float mx0 = -1e30f, mx1 = -1e30f;
                #pragma unroll
                for (int nt = 0; nt < 4; nt++) {
                    #pragma unroll
                    for (int jj = 0; jj < 4; jj++) sacc[nt][jj] *= SCL;
                    mx0 = fmaxf(mx0, fmaxf(sacc[nt][0], sacc[nt][1]));
                    mx1 = fmaxf(mx1, fmaxf(sacc[nt][2], sacc[nt][3]));
                }
                mx0 = fmaxf(mx0, __shfl_xor_sync(0xffffffffu, mx0, 1));
                mx0 = fmaxf(mx0, __shfl_xor_sync(0xffffffffu, mx0, 2));
                mx1 = fmaxf(mx1, __shfl_xor_sync(0xffffffffu, mx1, 1));
                mx1 = fmaxf(mx1, __shfl_xor_sync(0xffffffffu, mx1, 2));
                if (t4 == 0) {
                    smf[F_MX + ni * 64 + r0] = mx0;
                    smf[F_MX + ni * 64 + r1] = mx1;
                }
                asm volatile("bar.sync 1, 256;" ::: "memory");
                float Mn0 = fmaxf(M0, fmaxf(mx0, smf[F_MX + (1 - ni) * 64 + r0]));
                float Mn1 = fmaxf(M1, fmaxf(mx1, smf[F_MX + (1 - ni) * 64 + r1]));
                float f0 = exp2f(M0 - Mn0), f1 = exp2f(M1 - Mn1);
                M0 = Mn0; M1 = Mn1;
                if (ni == 0 && t4 == 0) {
                    smf[(i & 1) * 64 + r0] = f0;
                    smf[(i & 1) * 64 + r1] = f1;
                }
                float s0 = 0.f, s1 = 0.f;
                __half* Pb = smh + ((i & 1) ? OFF_P1 : OFF_P0);
                #pragma unroll
                for (int nt = 0; nt < 4; nt++) {
                    float p00 = exp2f(sacc[nt][0] - Mn0);
                    float p01 = exp2f(sacc[nt][1] - Mn0);
                    float p10 = exp2f(sacc[nt][2] - Mn1);
                    float p11 = exp2f(sacc[nt][3] - Mn1);
                    s0 += p00 + p01; s1 += p10 + p11;
                    __half2 u0 = __floats2half2_rn(p00, p01);
                    __half2 u1 = __floats2half2_rn(p10, p11);
                    int ccol = ni * 32 + nt * 8 + t4 * 2;
                    *(__half2*)&Pb[r0 * PPH + ccol] = u0;
                    *(__half2*)&Pb[r1 * PPH + ccol] = u1;
                }
                s0 += __shfl_xor_sync(0xffffffffu, s0, 1);
                s0 += __shfl_xor_sync(0xffffffffu, s0, 2);
                s1 += __shfl_xor_sync(0xffffffffu, s1, 1);
                s1 += __shfl_xor_sync(0xffffffffu, s1, 2);
                L0 = L0 * f0 + s0;
                L1 = L1 * f1 + s1;
            } else {
                if (t4 == 0) {
                    smf[F_LS + ni * 64 + r0] = L0;
                    smf[F_LS + ni * 64 + r1] = L1;
                    if (ni == 0) {
                        smf[F_MX + r0] = M0;
                        smf[F_MX + r1] = M1;
                    }
                }
            }
        } else {
            if (i < NIT) {
                copyV16(Vtg, ktbase + i, smh + ((i & 1) ? OFF_V1 : OFF_V0), t - 256);
                cpcommit();
            }
            if (i >= 1) {
                int j = i - 1;
                float f0 = smf[(j & 1) * 64 + cr0];
                float f1 = smf[(j & 1) * 64 + cr1];
                bool nor = (f0 == 1.f) && (f1 == 1.f);
                if (__ballot_sync(0xffffffffu, nor) != 0xffffffffu) {
                    #pragma unroll
                    for (int q = 0; q < 16; q++) {
                        oacc[q][0] *= f0; oacc[q][1] *= f0;
                        oacc[q][2] *= f1; oacc[q][3] *= f1;
                    }
                }
                uint32_t aP = (j & 1) ? aP1 : aP0;
                uint32_t aV = (j & 1) ? aV1 : aV0;
                #pragma unroll
                for (int km = 0; km < 4; km++) {
                    uint32_t pa0, pa1, pa2, pa3;
                    ldsm4(pa0, pa1, pa2, pa3, aP + km * 32);
                    #pragma unroll
                    for (int ct = 0; ct < 8; ct++) {
                        uint32_t v0, v1, v2, v3;
                        ldsm4(v0, v1, v2, v3, aV + ct * (16 * VPH * 2) + km * 32);
                        mma16(oacc[ct * 2],     pa0, pa1, pa2, pa3, v0, v1);
                        mma16(oacc[ct * 2 + 1], pa0, pa1, pa2, pa3, v2, v3);
                    }
                }
            }
        }
        cpwait<0>();
        __syncthreads();
    }

    // epilogue: consumers write UNNORMALIZED fp32 partials + per-row (M, L)
    if (!isProd) {
        float Lt0 = smf[F_LS + cr0] + smf[F_LS + 64 + cr0];
        float Lt1 = smf[F_LS + cr1] + smf[F_LS + 64 + cr1];
        float Mv0 = smf[F_MX + cr0];
        float Mv1 = smf[F_MX + cr1];
        float* OP = g_op + ((size_t)(half * Bn + b) * HWn + qbase) * Cc;
        #pragma unroll
        for (int q = 0; q < 16; q++) {
            int ch = cc * 128 + q * 8 + t4 * 2;
            *(float2*)&OP[(size_t)cr0 * Cc + ch] = make_float2(oacc[q][0], oacc[q][1]);
            *(float2*)&OP[(size_t)cr1 * Cc + ch] = make_float2(oacc[q][2], oacc[q][3]);
        }
        if (cc == 0 && t4 == 0) {
            size_t mlbase = (size_t)(half * Bn + b) * HWn + qbase;
            g_ml[mlbase + cr0] = make_float2(Mv0, Lt0);
            g_ml[mlbase + cr1] = make_float2(Mv1, Lt1);
        }
    }
}

// ---------------- merge: combine the two KV halves (log-sum-exp) -----------------
__global__ __launch_bounds__(256) void merge_kernel() {
    int row = blockIdx.x * 4 + (threadIdx.x >> 6);       // [0, Bn*HWn)
    int ch  = (threadIdx.x & 63) * 4;
    const size_t HALF = (size_t)Bn * HWn;

    float2 ml0 = g_ml[row];
    float2 ml1 = g_ml[HALF + row];
    float M = fmaxf(ml0.x, ml1.x);
    float w0 = exp2f(ml0.x - M), w1 = exp2f(ml1.x - M);
    float inv = 1.0f / (w0 * ml0.y + w1 * ml1.y);

    float4 o0 = *(const float4*)&g_op[(size_t)row * Cc + ch];
    float4 o1 = *(const float4*)&g_op[(HALF + row) * Cc + ch];
    __half2 h0 = __floats2half2_rn((w0 * o0.x + w1 * o1.x) * inv,
                                   (w0 * o0.y + w1 * o1.y) * inv);
    __half2 h1 = __floats2half2_rn((w0 * o0.z + w1 * o1.z) * inv,
                                   (w0 * o0.w + w1 * o1.w) * inv);
    uint2 pk = { H2U(h0), H2U(h1) };
    *(uint2*)&g_aoh[(size_t)row * Cc + ch] = pk;
}

// ---------------- proj GEMM (fp16) + residual ------------------------------------
__global__ __launch_bounds__(256) void proj_kernel(const float* __restrict__ x,
                                                   const float* __restrict__ pb,
                                                   float* __restrict__ out) {
    extern __shared__ __align__(16) __half gsm[];
    int b = blockIdx.z;
    int om = blockIdx.y * 128;
    int pn = blockIdx.x * 128;
    const __half* Ag = g_pwh + (size_t)om * Cc;
    const __half* Bg = g_aoh + (size_t)b * HWn * Cc + (size_t)pn * Cc;

    float acc[2][8][4] = {};
    gemm16(Ag, Bg, gsm, acc);

    int t = threadIdx.x, wid = t >> 5, lane = t & 31, g = lane >> 2, t4 = lane & 3;
    int wm = (wid >> 1) * 32, wn = (wid & 1) * 64;

    #pragma unroll
    for (int mt = 0; mt < 2; mt++) {
        int o0 = om + wm + mt * 16 + g;
        float b0 = pb[o0], b1 = pb[o0 + 8];
        #pragma unroll
        for (int nt = 0; nt < 8; nt++) {
            int p0 = pn + wn + nt * 8 + t4 * 2;
            size_t off0 = ((size_t)b * Cc + o0) * HWn + p0;
            size_t off1 = ((size_t)b * Cc + o0 + 8) * HWn + p0;
            float2 x0 = *(const float2*)&x[off0];
            float2 x1 = *(const float2*)&x[off1];
            float2 v0 = { acc[mt][nt][0] + b0 + x0.x, acc[mt][nt][1] + b0 + x0.y };
            float2 v1 = { acc[mt][nt][2] + b1 + x1.x, acc[mt][nt][3] + b1 + x1.y };
            *(float2*)&out[off0] = v0;
            *(float2*)&out[off1] = v1;
        }
    }
}

// ---------------- launch ---------------------------------------------------------
extern "C" void kernel_launch(void* const* d_in, const int* in_sizes, int n_in,
                              void* d_out, int out_size) {
    const float* x  = (const float*)d_in[0];
    const float* nw = (const float*)d_in[1];
    const float* nb = (const float*)d_in[2];
    const float* qw = (const float*)d_in[3];
    const float* qb = (const float*)d_in[4];
    const float* pw = (const float*)d_in[5];
    const float* pb = (const float*)d_in[6];
    float* out = (float*)d_out;

    cudaFuncSetAttribute(flash_kernel, cudaFuncAttributeMaxDynamicSharedMemorySize,
                         SMEM_BYTES);
    cudaFuncSetAttribute(qkv_kernel, cudaFuncAttributeMaxDynamicSharedMemorySize,
                         GEMM_SMEM);
    cudaFuncSetAttribute(proj_kernel, cudaFuncAttributeMaxDynamicSharedMemorySize,
                         GEMM_SMEM);

    gn_stats<<<64 + 192, 1024>>>(x, qw, pw);
    gn_apply<<<512, 512>>>(x, nw, nb);
    qkv_kernel<<<dim3(6, 32, 8), 256, GEMM_SMEM>>>(qb);
    flash_kernel<<<dim3(64, 8, 2), 512, SMEM_BYTES>>>();
    merge_kernel<<<Bn * HWn / 4, 256>>>();
    proj_kernel<<<dim3(32, 2, 8), 256, GEMM_SMEM>>>(x, pb, out);
}

// round 15
// speedup vs baseline: 1.1198x; 1.0052x over previous
#include <cuda_runtime.h>
#include <cuda_fp16.h>
#include <cstdint>

#define Bn  8
#define Cc  256
#define HWn 4096

// ---- flash smem layout (half offsets) ----
#define QPH 264
#define VPH 72
#define PPH 72
#define OFF_Q  0
#define OFF_K0 16896
#define OFF_K1 33792
#define OFF_V0 50688
#define OFF_V1 69120
#define OFF_P0 87552
#define OFF_P1 92160
#define OFF_F  96768
#define F_MX 128
#define F_LS 256
#define SMEM_BYTES (OFF_F * 2 + 384 * 4)   // 195072 B

// ---- fp16 GEMM tiles ----
#define GP 264
#define GEMM_SMEM (2 * 128 * GP * 2)       // 135168 B (qkv: 128x128 tile)
#define PROJ_SMEM (192 * GP * 2)           // 101376 B (proj: 128x64 tile)

// ---------------- scratch -----------------------------------------------------
__device__ __half g_xnh[(size_t)Bn * HWn * Cc];
__device__ __half g_qwh[768 * 256];
__device__ __half g_pwh[256 * 256];
__device__ __half g_q [(size_t)Bn * HWn * Cc];
__device__ __half g_k [(size_t)Bn * HWn * Cc];
__device__ __half g_vt[(size_t)Bn * Cc * HWn];
__device__ __half g_aoh[(size_t)Bn * HWn * Cc];
__device__ __half g_oph[(size_t)2 * Bn * HWn * Cc];   // normalized partial O, fp16
__device__ float2 g_ml [(size_t)2 * Bn * HWn];        // per-row (M, L) per half
__device__ float2 g_mr [64];                          // per-(b,g) mean/rstd

// ---------------- helpers ------------------------------------------------------
__device__ __forceinline__ void mma16(float c[4], uint32_t a0, uint32_t a1, uint32_t a2,
                                      uint32_t a3, uint32_t b0, uint32_t b1) {
    asm("mma.sync.aligned.m16n8k16.row.col.f32.f16.f16.f32 "
        "{%0,%1,%2,%3},{%4,%5,%6,%7},{%8,%9},{%0,%1,%2,%3};"
        : "+f"(c[0]), "+f"(c[1]), "+f"(c[2]), "+f"(c[3])
        : "r"(a0), "r"(a1), "r"(a2), "r"(a3), "r"(b0), "r"(b1));
}
__device__ __forceinline__ void ldsm4(uint32_t& r0, uint32_t& r1, uint32_t& r2,
                                      uint32_t& r3, uint32_t a) {
    asm volatile("ldmatrix.sync.aligned.m8n8.x4.shared.b16 {%0,%1,%2,%3}, [%4];"
        : "=r"(r0), "=r"(r1), "=r"(r2), "=r"(r3) : "r"(a));
}
#define H2U(x) (*(const uint32_t*)&(x))

__device__ __forceinline__ void cp16(void* dst, const void* src) {
    uint32_t d = (uint32_t)__cvta_generic_to_shared(dst);
    asm volatile("cp.async.cg.shared.global [%0], [%1], 16;\n" :: "r"(d), "l"(src));
}
__device__ __forceinline__ void cpcommit() { asm volatile("cp.async.commit_group;\n"); }
template<int N> __device__ __forceinline__ void cpwait() {
    asm volatile("cp.async.wait_group %0;\n" :: "n"(N));
}

// ---------------- GN stats (64 blocks) + fused weight conversion (192 blocks) ----
__global__ __launch_bounds__(1024) void gn_stats(const float* __restrict__ x,
                                                 const float* __restrict__ qw,
                                                 const float* __restrict__ pw) {
    if (blockIdx.x >= 64) {
        int i = (blockIdx.x - 64) * 1024 + threadIdx.x;
        g_qwh[i] = __float2half(qw[i]);
        if (i < 256 * 256) g_pwh[i] = __float2half(pw[i]);
        return;
    }
    int b = blockIdx.x >> 3, g = blockIdx.x & 7;
    const float4* xb = (const float4*)(x + ((size_t)b * Cc + (size_t)g * 32) * HWn);
    const int N4 = 32 * HWn / 4;

    float s = 0.f, ss = 0.f;
    for (int i = threadIdx.x; i < N4; i += 1024) {
        float4 v = xb[i];
        s  += v.x + v.y + v.z + v.w;
        ss += v.x * v.x + v.y * v.y + v.z * v.z + v.w * v.w;
    }
    __shared__ float rs[32], rss[32];
    int lane = threadIdx.x & 31, wid = threadIdx.x >> 5;
    #pragma unroll
    for (int o = 16; o; o >>= 1) {
        s  += __shfl_down_sync(0xffffffffu, s, o);
        ss += __shfl_down_sync(0xffffffffu, ss, o);
    }
    if (lane == 0) { rs[wid] = s; rss[wid] = ss; }
    __syncthreads();
    if (wid == 0) {
        s  = rs[lane];
        ss = rss[lane];
        #pragma unroll
        for (int o = 16; o; o >>= 1) {
            s  += __shfl_down_sync(0xffffffffu, s, o);
            ss += __shfl_down_sync(0xffffffffu, ss, o);
        }
        if (lane == 0) {
            const float NEL = 32.0f * HWn;
            float mean = s / NEL;
            float var  = ss / NEL - mean * mean;
            g_mr[blockIdx.x] = make_float2(mean, rsqrtf(var + 1e-5f));
        }
    }
}

// ---------------- GN apply (512 blocks) -------------------------------------------
__global__ __launch_bounds__(512) void gn_apply(const float* __restrict__ x,
                                                const float* __restrict__ w,
                                                const float* __restrict__ bv) {
    __shared__ float sm[32][132];
    __shared__ float ws[32], bs[32];
    int bg = blockIdx.x >> 3, slice = blockIdx.x & 7;
    int b = bg >> 3, g = bg & 7;
    const float* xb = x + ((size_t)b * Cc + (size_t)g * 32) * HWn;
    int tid = threadIdx.x;
    float2 mr = g_mr[bg];
    float mean = mr.x, rstd = mr.y;
    if (tid < 32) { ws[tid] = w[g * 32 + tid]; bs[tid] = bv[g * 32 + tid]; }

    __half* out = g_xnh + (size_t)b * HWn * Cc + g * 32;
    int c  = tid >> 4, pl = (tid & 15) * 8;
    int pl2 = tid >> 2, c8 = (tid & 3) * 8;
    int pbase = slice * 512;

    for (int p0 = pbase; p0 < pbase + 512; p0 += 128) {
        float4 v0 = *(const float4*)(xb + (size_t)c * HWn + p0 + pl);
        float4 v1 = *(const float4*)(xb + (size_t)c * HWn + p0 + pl + 4);
        __syncthreads();
        *(float4*)&sm[c][pl]     = v0;
        *(float4*)&sm[c][pl + 4] = v1;
        __syncthreads();
        __half2 h[4];
        #pragma unroll
        for (int jj = 0; jj < 4; jj++) {
            int c0 = c8 + jj * 2;
            float a0 = (sm[c0][pl2]     - mean) * rstd * ws[c0]     + bs[c0];
            float a1 = (sm[c0 + 1][pl2] - mean) * rstd * ws[c0 + 1] + bs[c0 + 1];
            h[jj] = __floats2half2_rn(a0, a1);
        }
        *(uint4*)&out[(size_t)(p0 + pl2) * Cc + c8] = *(uint4*)h;
    }
}

// ---------------- fp16 NT GEMM core (128x128, qkv) --------------------------------
__device__ __forceinline__ void gemm16(const __half* __restrict__ Ag,
                                       const __half* __restrict__ Bg,
                                       __half* gsm, float acc[2][8][4]) {
    int t = threadIdx.x;
    #pragma unroll
    for (int i = 0; i < 16; i++) {
        int idx = t + 256 * i;
        int row = idx >> 5, pc = idx & 31;
        cp16(gsm + row * GP + pc * 8, Ag + (size_t)row * 256 + pc * 8);
        cp16(gsm + 128 * GP + row * GP + pc * 8, Bg + (size_t)row * 256 + pc * 8);
    }
    cpcommit();
    cpwait<0>();
    __syncthreads();

    int wid = t >> 5, lane = t & 31;
    int wm = (wid >> 1) * 32, wn = (wid & 1) * 64;
    uint32_t sb = (uint32_t)__cvta_generic_to_shared(gsm);
    uint32_t aA = sb + (uint32_t)((wm + (lane & 15)) * GP + (lane >> 4) * 8) * 2;
    uint32_t rowKV = (uint32_t)(((lane >> 4) << 3) + (lane & 7));
    uint32_t colHi = (uint32_t)(((lane >> 3) & 1) << 3);
    uint32_t aB = sb + (uint32_t)(128 * GP + (wn + rowKV) * GP + colHi) * 2;

    #pragma unroll
    for (int ks = 0; ks < 16; ks++) {
        uint32_t a[2][4];
        ldsm4(a[0][0], a[0][1], a[0][2], a[0][3], aA + ks * 32);
        ldsm4(a[1][0], a[1][1], a[1][2], a[1][3], aA + 16 * GP * 2 + ks * 32);
        #pragma unroll
        for (int ng = 0; ng < 4; ng++) {
            uint32_t b0, b1, b2, b3;
            ldsm4(b0, b1, b2, b3, aB + ng * (16 * GP * 2) + ks * 32);
            #pragma unroll
            for (int mt = 0; mt < 2; mt++) {
                mma16(acc[mt][ng * 2],     a[mt][0], a[mt][1], a[mt][2], a[mt][3], b0, b1);
                mma16(acc[mt][ng * 2 + 1], a[mt][0], a[mt][1], a[mt][2], a[mt][3], b2, b3);
            }
        }
    }
}

// ---------------- QKV GEMM ---------------------------------------------------------
__global__ __launch_bounds__(256) void qkv_kernel(const float* __restrict__ bias) {
    extern __shared__ __align__(16) __half gsm[];
    int b = blockIdx.z;
    int pm = blockIdx.y * 128;
    int on = blockIdx.x * 128;
    const __half* Ag = g_xnh + (size_t)b * HWn * Cc + (size_t)pm * Cc;
    const __half* Bg = g_qwh + (size_t)on * Cc;

    float acc[2][8][4] = {};
    gemm16(Ag, Bg, gsm, acc);

    int t = threadIdx.x, wid = t >> 5, lane = t & 31, g = lane >> 2, t4 = lane & 3;
    int wm = (wid >> 1) * 32, wn = (wid & 1) * 64;

    if (on < 512) {
        __half* dst = ((on < 256) ? g_q : g_k) + (size_t)b * HWn * Cc;
        int obase = on & 255;
        #pragma unroll
        for (int nt = 0; nt < 8; nt++) {
            int ocol = wn + nt * 8 + t4 * 2;
            float2 bb = *(const float2*)&bias[on + ocol];
            #pragma unroll
            for (int mt = 0; mt < 2; mt++) {
                int p0 = pm + wm + mt * 16 + g;
                __half2 v0 = __floats2half2_rn(acc[mt][nt][0] + bb.x, acc[mt][nt][1] + bb.y);
                __half2 v1 = __floats2half2_rn(acc[mt][nt][2] + bb.x, acc[mt][nt][3] + bb.y);
                *(__half2*)&dst[(size_t)p0 * Cc + obase + ocol]       = v0;
                *(__half2*)&dst[(size_t)(p0 + 8) * Cc + obase + ocol] = v1;
            }
        }
    } else {
        __half* dst = g_vt + (size_t)b * Cc * HWn;
        #pragma unroll
        for (int nt = 0; nt < 8; nt++) {
            int ocol = wn + nt * 8 + t4 * 2;
            int c0 = (on - 512) + ocol;
            float2 bb = *(const float2*)&bias[on + ocol];
            #pragma unroll
            for (int mt = 0; mt < 2; mt++) {
                int p0 = pm + wm + mt * 16 + g;
                dst[(size_t)c0 * HWn + p0]           = __float2half(acc[mt][nt][0] + bb.x);
                dst[(size_t)(c0 + 1) * HWn + p0]     = __float2half(acc[mt][nt][1] + bb.y);
                dst[(size_t)c0 * HWn + p0 + 8]       = __float2half(acc[mt][nt][2] + bb.x);
                dst[(size_t)(c0 + 1) * HWn + p0 + 8] = __float2half(acc[mt][nt][3] + bb.y);
            }
        }
    }
}

// ---------------- flash: warp-specialized, split-KV (m-half per CTA) -------------
__device__ __forceinline__ void copyK16(const __half* Kg, int kt, __half* kb, int t) {
    #pragma unroll
    for (int i = 0; i < 8; i++) {
        int idx = t + 256 * i;
        int row = idx >> 5, pc = idx & 31;
        cp16(kb + row * QPH + pc * 8, Kg + (size_t)(kt * 64 + row) * Cc + pc * 8);
    }
}
__device__ __forceinline__ void copyV16(const __half* Vtg, int kt, __half* vb, int t) {
    #pragma unroll
    for (int i = 0; i < 8; i++) {
        int idx = t + 256 * i;
        int c = idx >> 3, pc = idx & 7;
        cp16(vb + c * VPH + pc * 8, Vtg + (size_t)c * HWn + kt * 64 + pc * 8);
    }
}

__global__ void __launch_bounds__(512, 1) flash_kernel() {
    extern __shared__ __align__(16) __half smh[];
    float* smf = (float*)(smh + OFF_F);
    int b = blockIdx.y;
    int half = blockIdx.z;
    int qbase = blockIdx.x * 64;
    const int NIT = 32;
    int ktbase = half * NIT;
    const __half* Qg  = g_q  + (size_t)b * HWn * Cc + (size_t)qbase * Cc;
    const __half* Kg  = g_k  + (size_t)b * HWn * Cc;
    const __half* Vtg = g_vt + (size_t)b * Cc * HWn;

    int t = threadIdx.x;
    int wid = t >> 5, lane = t & 31, g = lane >> 2, t4 = lane & 3;
    bool isProd = (wid < 8);
    uint32_t sb = (uint32_t)__cvta_generic_to_shared(smh);
    uint32_t rowKV = (uint32_t)(((lane >> 4) << 3) + (lane & 7));
    uint32_t colHi = (uint32_t)(((lane >> 3) & 1) << 3);

    int mi = (wid & 7) >> 1, ni = wid & 1;
    int wm = mi * 16;
    int r0 = wm + g, r1 = r0 + 8;
    uint32_t aQ  = sb + (uint32_t)(OFF_Q  + (wm + (lane & 15)) * QPH + (lane >> 4) * 8) * 2;
    uint32_t aK0 = sb + (uint32_t)(OFF_K0 + (ni * 32 + rowKV) * QPH + colHi) * 2;
    uint32_t aK1 = sb + (uint32_t)(OFF_K1 + (ni * 32 + rowKV) * QPH + colHi) * 2;

    int cw = wid - 8;
    int cq = (cw > 0 ? cw : 0) >> 1, cc = cw & 1;
    int cr0 = cq * 16 + g, cr1 = cr0 + 8;
    uint32_t aP0 = sb + (uint32_t)(OFF_P0 + (cq * 16 + (lane & 15)) * PPH + (lane >> 4) * 8) * 2;
    uint32_t aP1 = sb + (uint32_t)(OFF_P1 + (cq * 16 + (lane & 15)) * PPH + (lane >> 4) * 8) * 2;
    uint32_t aV0 = sb + (uint32_t)(OFF_V0 + (cc * 128 + rowKV) * VPH + colHi) * 2;
    uint32_t aV1 = sb + (uint32_t)(OFF_V1 + (cc * 128 + rowKV) * VPH + colHi) * 2;

    float oacc[16][4] = {};
    float M0 = -1e30f, M1 = -1e30f, L0 = 0.f, L1 = 0.f;

    if (isProd) copyK16(Kg, ktbase, smh + OFF_K0, t);
    else        copyK16(Qg, 0, smh + OFF_Q, t - 256);
    cpcommit();
    cpwait<0>();
    __syncthreads();

    const float SCL = 0.09016844f;   // log2(e)/16

    for (int i = 0; i <= NIT; i++) {
        if (isProd) {
            if (i < NIT - 1) {
                copyK16(Kg, ktbase + i + 1, smh + (((i + 1) & 1) ? OFF_K1 : OFF_K0), t);
                cpcommit();
            }
            if (i < NIT) {
                uint32_t kb = (i & 1) ? aK1 : aK0;
                float sacc[4][4] = {};
                #pragma unroll
                for (int ks = 0; ks < 16; ks++) {
                    uint32_t q0, q1, q2, q3;
                    ldsm4(q0, q1, q2, q3, aQ + ks * 32);
                    #pragma unroll
                    for (int ntp = 0; ntp < 2; ntp++) {
                        uint32_t b0, b1, b2, b3;
                        ldsm4(b0, b1, b2, b3, kb + ntp * (16 * QPH * 2) + ks * 32);
                        mma16(sacc[ntp * 2],     q0, q1, q2, q3, b0, b1);
                        mma16(sacc[ntp * 2 + 1], q0, q1, q2, q3, b2, b3);
                    }
                }
                float mx0 = -1e30f, mx1 = -1e30f;
                #pragma unroll
                for (int nt = 0; nt < 4; nt++) {
                    #pragma unroll
                    for (int jj = 0; jj < 4; jj++) sacc[nt][jj] *= SCL;
                    mx0 = fmaxf(mx0, fmaxf(sacc[nt][0], sacc[nt][1]));
                    mx1 = fmaxf(mx1, fmaxf(sacc[nt][2], sacc[nt][3]));
                }
                mx0 = fmaxf(mx0, __shfl_xor_sync(0xffffffffu, mx0, 1));
                mx0 = fmaxf(mx0, __shfl_xor_sync(0xffffffffu, mx0, 2));
                mx1 = fmaxf(mx1, __shfl_xor_sync(0xffffffffu, mx1, 1));
                mx1 = fmaxf(mx1, __shfl_xor_sync(0xffffffffu, mx1, 2));
                if (t4 == 0) {
                    smf[F_MX + ni * 64 + r0] = mx0;
                    smf[F_MX + ni * 64 + r1] = mx1;
                }
                asm volatile("bar.sync 1, 256;" ::: "memory");
                float Mn0 = fmaxf(M0, fmaxf(mx0, smf[F_MX + (1 - ni) * 64 + r0]));
                float Mn1 = fmaxf(M1, fmaxf(mx1, smf[F_MX + (1 - ni) * 64 + r1]));
                float f0 = exp2f(M0 - Mn0), f1 = exp2f(M1 - Mn1);
                M0 = Mn0; M1 = Mn1;
                if (ni == 0 && t4 == 0) {
                    smf[(i & 1) * 64 + r0] = f0;
                    smf[(i & 1) * 64 + r1] = f1;
                }
                float s0 = 0.f, s1 = 0.f;
                __half* Pb = smh + ((i & 1) ? OFF_P1 : OFF_P0);
                #pragma unroll
                for (int nt = 0; nt < 4; nt++) {
                    float p00 = exp2f(sacc[nt][0] - Mn0);
                    float p01 = exp2f(sacc[nt][1] - Mn0);
                    float p10 = exp2f(sacc[nt][2] - Mn1);
                    float p11 = exp2f(sacc[nt][3] - Mn1);
                    s0 += p00 + p01; s1 += p10 + p11;
                    __half2 u0 = __floats2half2_rn(p00, p01);
                    __half2 u1 = __floats2half2_rn(p10, p11);
                    int ccol = ni * 32 + nt * 8 + t4 * 2;
                    *(__half2*)&Pb[r0 * PPH + ccol] = u0;
                    *(__half2*)&Pb[r1 * PPH + ccol] = u1;
                }
                s0 += __shfl_xor_sync(0xffffffffu, s0, 1);
                s0 += __shfl_xor_sync(0xffffffffu, s0, 2);
                s1 += __shfl_xor_sync(0xffffffffu, s1, 1);
                s1 += __shfl_xor_sync(0xffffffffu, s1, 2);
                L0 = L0 * f0 + s0;
                L1 = L1 * f1 + s1;
            } else {
                if (t4 == 0) {
                    smf[F_LS + ni * 64 + r0] = L0;
                    smf[F_LS + ni * 64 + r1] = L1;
                    if (ni == 0) {
                        smf[F_MX + r0] = M0;
                        smf[F_MX + r1] = M1;
                    }
                }
            }
        } else {
            if (i < NIT) {
                copyV16(Vtg, ktbase + i, smh + ((i & 1) ? OFF_V1 : OFF_V0), t - 256);
                cpcommit();
            }
            if (i >= 1) {
                int j = i - 1;
                float f0 = smf[(j & 1) * 64 + cr0];
                float f1 = smf[(j & 1) * 64 + cr1];
                bool nor = (f0 == 1.f) && (f1 == 1.f);
                if (__ballot_sync(0xffffffffu, nor) != 0xffffffffu) {
                    #pragma unroll
                    for (int q = 0; q < 16; q++) {
                        oacc[q][0] *= f0; oacc[q][1] *= f0;
                        oacc[q][2] *= f1; oacc[q][3] *= f1;
                    }
                }
                uint32_t aP = (j & 1) ? aP1 : aP0;
                uint32_t aV = (j & 1) ? aV1 : aV0;
                #pragma unroll
                for (int km = 0; km < 4; km++) {
                    uint32_t pa0, pa1, pa2, pa3;
                    ldsm4(pa0, pa1, pa2, pa3, aP + km * 32);
                    #pragma unroll
                    for (int ct = 0; ct < 8; ct++) {
                        uint32_t v0, v1, v2, v3;
                        ldsm4(v0, v1, v2, v3, aV + ct * (16 * VPH * 2) + km * 32);
                        mma16(oacc[ct * 2],     pa0, pa1, pa2, pa3, v0, v1);
                        mma16(oacc[ct * 2 + 1], pa0, pa1, pa2, pa3, v2, v3);
                    }
                }
            }
        }
        cpwait<0>();
        __syncthreads();
    }

    // epilogue: consumers write NORMALIZED fp16 partials + per-row (M, L)
    if (!isProd) {
        float Lt0 = smf[F_LS + cr0] + smf[F_LS + 64 + cr0];
        float Lt1 = smf[F_LS + cr1] + smf[F_LS + 64 + cr1];
        float Mv0 = smf[F_MX + cr0];
        float Mv1 = smf[F_MX + cr1];
        float inv0 = 1.0f / Lt0, inv1 = 1.0f / Lt1;
        __half* OP = g_oph + ((size_t)(half * Bn + b) * HWn + qbase) * Cc;
        #pragma unroll
        for (int q = 0; q < 16; q++) {
            int ch = cc * 128 + q * 8 + t4 * 2;
            __half2 v0 = __floats2half2_rn(oacc[q][0] * inv0, oacc[q][1] * inv0);
            __half2 v1 = __floats2half2_rn(oacc[q][2] * inv1, oacc[q][3] * inv1);
            *(__half2*)&OP[(size_t)cr0 * Cc + ch] = v0;
            *(__half2*)&OP[(size_t)cr1 * Cc + ch] = v1;
        }
        if (cc == 0 && t4 == 0) {
            size_t mlbase = (size_t)(half * Bn + b) * HWn + qbase;
            g_ml[mlbase + cr0] = make_float2(Mv0, Lt0);
            g_ml[mlbase + cr1] = make_float2(Mv1, Lt1);
        }
    }
}

// ---------------- merge: weighted sum of normalized fp16 halves ------------------
__global__ __launch_bounds__(256) void merge_kernel() {
    int row = blockIdx.x * 4 + (threadIdx.x >> 6);
    int ch  = (threadIdx.x & 63) * 4;
    const size_t HALF = (size_t)Bn * HWn;

    float2 ml0 = g_ml[row];
    float2 ml1 = g_ml[HALF + row];
    float M = fmaxf(ml0.x, ml1.x);
    float w0 = exp2f(ml0.x - M) * ml0.y;
    float w1 = exp2f(ml1.x - M) * ml1.y;
    float inv = 1.0f / (w0 + w1);
    float c0 = w0 * inv, c1 = w1 * inv;

    uint2 p0 = *(const uint2*)&g_oph[(size_t)row * Cc + ch];
    uint2 p1 = *(const uint2*)&g_oph[(HALF * Cc) + (size_t)row * Cc + ch];
    float2 a0 = __half22float2(*(const __half2*)&p0.x);
    float2 a1 = __half22float2(*(const __half2*)&p0.y);
    float2 b0 = __half22float2(*(const __half2*)&p1.x);
    float2 b1 = __half22float2(*(const __half2*)&p1.y);
    __half2 h0 = __floats2half2_rn(c0 * a0.x + c1 * b0.x, c0 * a0.y + c1 * b0.y);
    __half2 h1 = __floats2half2_rn(c0 * a1.x + c1 * b1.x, c0 * a1.y + c1 * b1.y);
    uint2 pk = { H2U(h0), H2U(h1) };
    *(uint2*)&g_aoh[(size_t)row * Cc + ch] = pk;
}

// ---------------- proj GEMM (fp16, 128x64 tiles) + residual -----------------------
__global__ __launch_bounds__(256) void proj_kernel(const float* __restrict__ x,
                                                   const float* __restrict__ pb,
                                                   float* __restrict__ out) {
    extern __shared__ __align__(16) __half gsm[];
    int b = blockIdx.z;
    int om = blockIdx.y * 128;
    int pn = blockIdx.x * 64;
    const __half* Ag = g_pwh + (size_t)om * Cc;
    const __half* Bg = g_aoh + (size_t)b * HWn * Cc + (size_t)pn * Cc;

    int t = threadIdx.x;
    // loads: A 128 rows (16 pieces/thread), B 64 rows (8 pieces/thread)
    #pragma unroll
    for (int i = 0; i < 16; i++) {
        int idx = t + 256 * i;
        int row = idx >> 5, pc = idx & 31;
        cp16(gsm + row * GP + pc * 8, Ag + (size_t)row * 256 + pc * 8);
    }
    #pragma unroll
    for (int i = 0; i < 8; i++) {
        int idx = t + 256 * i;
        int row = idx >> 5, pc = idx & 31;
        cp16(gsm + 128 * GP + row * GP + pc * 8, Bg + (size_t)row * 256 + pc * 8);
    }
    cpcommit();
    cpwait<0>();
    __syncthreads();

    int wid = t >> 5, lane = t & 31, g = lane >> 2, t4 = lane & 3;
    int wm = (wid >> 1) * 32, wn = (wid & 1) * 32;
    uint32_t sb = (uint32_t)__cvta_generic_to_shared(gsm);
    uint32_t aA = sb + (uint32_t)((wm + (lane & 15)) * GP + (lane >> 4) * 8) * 2;
    uint32_t rowKV = (uint32_t)(((lane >> 4) << 3) + (lane & 7));
    uint32_t colHi = (uint32_t)(((lane >> 3) & 1) << 3);
    uint32_t aB = sb + (uint32_t)(128 * GP + (wn + rowKV) * GP + colHi) * 2;

    float acc[2][4][4] = {};
    #pragma unroll
    for (int ks = 0; ks < 16; ks++) {
        uint32_t a[2][4];
        ldsm4(a[0][0], a[0][1], a[0][2], a[0][3], aA + ks * 32);
        ldsm4(a[1][0], a[1][1], a[1][2], a[1][3], aA + 16 * GP * 2 + ks * 32);
        #pragma unroll
        for (int ng = 0; ng < 2; ng++) {
            uint32_t b0, b1, b2, b3;
            ldsm4(b0, b1, b2, b3, aB + ng * (16 * GP * 2) + ks * 32);
            #pragma unroll
            for (int mt = 0; mt < 2; mt++) {
                mma16(acc[mt][ng * 2],     a[mt][0], a[mt][1], a[mt][2], a[mt][3], b0, b1);
                mma16(acc[mt][ng * 2 + 1], a[mt][0], a[mt][1], a[mt][2], a[mt][3], b2, b3);
            }
        }
    }

    #pragma unroll
    for (int mt = 0; mt < 2; mt++) {
        int o0 = om + wm + mt * 16 + g;
        float b0 = pb[o0], b1 = pb[o0 + 8];
        #pragma unroll
        for (int nt = 0; nt < 4; nt++) {
            int p0 = pn + wn + nt * 8 + t4 * 2;
            size_t off0 = ((size_t)b * Cc + o0) * HWn + p0;
            size_t off1 = ((size_t)b * Cc + o0 + 8) * HWn + p0;
            float2 x0 = *(const float2*)&x[off0];
            float2 x1 = *(const float2*)&x[off1];
            float2 v0 = { acc[mt][nt][0] + b0 + x0.x, acc[mt][nt][1] + b0 + x0.y };
            float2 v1 = { acc[mt][nt][2] + b1 + x1.x, acc[mt][nt][3] + b1 + x1.y };
            *(float2*)&out[off0] = v0;
            *(float2*)&out[off1] = v1;
        }
    }
}

// ---------------- launch ---------------------------------------------------------
extern "C" void kernel_launch(void* const* d_in, const int* in_sizes, int n_in,
                              void* d_out, int out_size) {
    const float* x  = (const float*)d_in[0];
    const float* nw = (const float*)d_in[1];
    const float* nb = (const float*)d_in[2];
    const float* qw = (const float*)d_in[3];
    const float* qb = (const float*)d_in[4];
    const float* pw = (const float*)d_in[5];
    const float* pb = (const float*)d_in[6];
    float* out = (float*)d_out;

    cudaFuncSetAttribute(flash_kernel, cudaFuncAttributeMaxDynamicSharedMemorySize,
                         SMEM_BYTES);
    cudaFuncSetAttribute(qkv_kernel, cudaFuncAttributeMaxDynamicSharedMemorySize,
                         GEMM_SMEM);
    cudaFuncSetAttribute(proj_kernel, cudaFuncAttributeMaxDynamicSharedMemorySize,
                         PROJ_SMEM);

    gn_stats<<<64 + 192, 1024>>>(x, qw, pw);
    gn_apply<<<512, 512>>>(x, nw, nb);
    qkv_kernel<<<dim3(6, 32, 8), 256, GEMM_SMEM>>>(qb);
    flash_kernel<<<dim3(64, 8, 2), 512, SMEM_BYTES>>>();
    merge_kernel<<<Bn * HWn / 4, 256>>>();
    proj_kernel<<<dim3(64, 2, 8), 256, PROJ_SMEM>>>(x, pb, out);
}

// round 16
// speedup vs baseline: 1.3888x; 1.2402x over previous
#include <cuda_runtime.h>
#include <cuda_fp16.h>
#include <cstdint>

#define Bn  8
#define Cc  256
#define HWn 4096

// ---- flash smem layout (half offsets): Br=128, K chunk 64, full V ----
#define QPH 264
#define VPH 72
#define OFF_Q  0
#define OFF_K0 33792                    // 128*264
#define OFF_K1 50688                    // +64*264
#define OFF_V0 67584
#define OFF_V1 86016                    // +256*72
#define FTOT   104448                   // halves
#define SMEM_BYTES (FTOT * 2)           // 208896 B

// ---- fp16 GEMM tiles ----
#define GP 264
#define GEMM_SMEM (2 * 128 * GP * 2)    // 135168 B (qkv)
#define PROJ_SMEM (192 * GP * 2)        // 101376 B (proj)

#define NSPLIT 4
#define NIT    16                       // 4096 / NSPLIT / 64

// ---------------- scratch -----------------------------------------------------
__device__ __half g_xnh[(size_t)Bn * HWn * Cc];
__device__ __half g_qwh[768 * 256];
__device__ __half g_pwh[256 * 256];
__device__ __half g_q [(size_t)Bn * HWn * Cc];
__device__ __half g_k [(size_t)Bn * HWn * Cc];
__device__ __half g_vt[(size_t)Bn * Cc * HWn];
__device__ __half g_aoh[(size_t)Bn * HWn * Cc];
__device__ __half g_oph[(size_t)NSPLIT * Bn * HWn * Cc];   // normalized partials
__device__ float2 g_ml [(size_t)NSPLIT * Bn * HWn];        // per-row (M, L)
__device__ float2 g_mr [64];

// ---------------- helpers ------------------------------------------------------
__device__ __forceinline__ void mma16(float c[4], uint32_t a0, uint32_t a1, uint32_t a2,
                                      uint32_t a3, uint32_t b0, uint32_t b1) {
    asm("mma.sync.aligned.m16n8k16.row.col.f32.f16.f16.f32 "
        "{%0,%1,%2,%3},{%4,%5,%6,%7},{%8,%9},{%0,%1,%2,%3};"
        : "+f"(c[0]), "+f"(c[1]), "+f"(c[2]), "+f"(c[3])
        : "r"(a0), "r"(a1), "r"(a2), "r"(a3), "r"(b0), "r"(b1));
}
__device__ __forceinline__ void ldsm4(uint32_t& r0, uint32_t& r1, uint32_t& r2,
                                      uint32_t& r3, uint32_t a) {
    asm volatile("ldmatrix.sync.aligned.m8n8.x4.shared.b16 {%0,%1,%2,%3}, [%4];"
        : "=r"(r0), "=r"(r1), "=r"(r2), "=r"(r3) : "r"(a));
}
#define H2U(x) (*(const uint32_t*)&(x))

__device__ __forceinline__ void cp16(void* dst, const void* src) {
    uint32_t d = (uint32_t)__cvta_generic_to_shared(dst);
    asm volatile("cp.async.cg.shared.global [%0], [%1], 16;\n" :: "r"(d), "l"(src));
}
__device__ __forceinline__ void cpcommit() { asm volatile("cp.async.commit_group;\n"); }
template<int N> __device__ __forceinline__ void cpwait() {
    asm volatile("cp.async.wait_group %0;\n" :: "n"(N));
}

// ---------------- GN stats (64 blocks) + weight conversion (192 blocks) ----------
__global__ __launch_bounds__(1024) void gn_stats(const float* __restrict__ x,
                                                 const float* __restrict__ qw,
                                                 const float* __restrict__ pw) {
    if (blockIdx.x >= 64) {
        int i = (blockIdx.x - 64) * 1024 + threadIdx.x;
        g_qwh[i] = __float2half(qw[i]);
        if (i < 256 * 256) g_pwh[i] = __float2half(pw[i]);
        return;
    }
    int b = blockIdx.x >> 3, g = blockIdx.x & 7;
    const float4* xb = (const float4*)(x + ((size_t)b * Cc + (size_t)g * 32) * HWn);
    const int N4 = 32 * HWn / 4;

    float s = 0.f, ss = 0.f;
    for (int i = threadIdx.x; i < N4; i += 1024) {
        float4 v = xb[i];
        s  += v.x + v.y + v.z + v.w;
        ss += v.x * v.x + v.y * v.y + v.z * v.z + v.w * v.w;
    }
    __shared__ float rs[32], rss[32];
    int lane = threadIdx.x & 31, wid = threadIdx.x >> 5;
    #pragma unroll
    for (int o = 16; o; o >>= 1) {
        s  += __shfl_down_sync(0xffffffffu, s, o);
        ss += __shfl_down_sync(0xffffffffu, ss, o);
    }
    if (lane == 0) { rs[wid] = s; rss[wid] = ss; }
    __syncthreads();
    if (wid == 0) {
        s  = rs[lane];
        ss = rss[lane];
        #pragma unroll
        for (int o = 16; o; o >>= 1) {
            s  += __shfl_down_sync(0xffffffffu, s, o);
            ss += __shfl_down_sync(0xffffffffu, ss, o);
        }
        if (lane == 0) {
            const float NEL = 32.0f * HWn;
            float mean = s / NEL;
            float var  = ss / NEL - mean * mean;
            g_mr[blockIdx.x] = make_float2(mean, rsqrtf(var + 1e-5f));
        }
    }
}

// ---------------- GN apply (512 blocks) -------------------------------------------
__global__ __launch_bounds__(512) void gn_apply(const float* __restrict__ x,
                                                const float* __restrict__ w,
                                                const float* __restrict__ bv) {
    __shared__ float sm[32][132];
    __shared__ float ws[32], bs[32];
    int bg = blockIdx.x >> 3, slice = blockIdx.x & 7;
    int b = bg >> 3, g = bg & 7;
    const float* xb = x + ((size_t)b * Cc + (size_t)g * 32) * HWn;
    int tid = threadIdx.x;
    float2 mr = g_mr[bg];
    float mean = mr.x, rstd = mr.y;
    if (tid < 32) { ws[tid] = w[g * 32 + tid]; bs[tid] = bv[g * 32 + tid]; }

    __half* out = g_xnh + (size_t)b * HWn * Cc + g * 32;
    int c  = tid >> 4, pl = (tid & 15) * 8;
    int pl2 = tid >> 2, c8 = (tid & 3) * 8;
    int pbase = slice * 512;

    for (int p0 = pbase; p0 < pbase + 512; p0 += 128) {
        float4 v0 = *(const float4*)(xb + (size_t)c * HWn + p0 + pl);
        float4 v1 = *(const float4*)(xb + (size_t)c * HWn + p0 + pl + 4);
        __syncthreads();
        *(float4*)&sm[c][pl]     = v0;
        *(float4*)&sm[c][pl + 4] = v1;
        __syncthreads();
        __half2 h[4];
        #pragma unroll
        for (int jj = 0; jj < 4; jj++) {
            int c0 = c8 + jj * 2;
            float a0 = (sm[c0][pl2]     - mean) * rstd * ws[c0]     + bs[c0];
            float a1 = (sm[c0 + 1][pl2] - mean) * rstd * ws[c0 + 1] + bs[c0 + 1];
            h[jj] = __floats2half2_rn(a0, a1);
        }
        *(uint4*)&out[(size_t)(p0 + pl2) * Cc + c8] = *(uint4*)h;
    }
}

// ---------------- fp16 NT GEMM core (128x128, qkv) --------------------------------
__device__ __forceinline__ void gemm16(const __half* __restrict__ Ag,
                                       const __half* __restrict__ Bg,
                                       __half* gsm, float acc[2][8][4]) {
    int t = threadIdx.x;
    #pragma unroll
    for (int i = 0; i < 16; i++) {
        int idx = t + 256 * i;
        int row = idx >> 5, pc = idx & 31;
        cp16(gsm + row * GP + pc * 8, Ag + (size_t)row * 256 + pc * 8);
        cp16(gsm + 128 * GP + row * GP + pc * 8, Bg + (size_t)row * 256 + pc * 8);
    }
    cpcommit();
    cpwait<0>();
    __syncthreads();

    int wid = t >> 5, lane = t & 31;
    int wm = (wid >> 1) * 32, wn = (wid & 1) * 64;
    uint32_t sb = (uint32_t)__cvta_generic_to_shared(gsm);
    uint32_t aA = sb + (uint32_t)((wm + (lane & 15)) * GP + (lane >> 4) * 8) * 2;
    uint32_t rowKV = (uint32_t)(((lane >> 4) << 3) + (lane & 7));
    uint32_t colHi = (uint32_t)(((lane >> 3) & 1) << 3);
    uint32_t aB = sb + (uint32_t)(128 * GP + (wn + rowKV) * GP + colHi) * 2;

    #pragma unroll
    for (int ks = 0; ks < 16; ks++) {
        uint32_t a[2][4];
        ldsm4(a[0][0], a[0][1], a[0][2], a[0][3], aA + ks * 32);
        ldsm4(a[1][0], a[1][1], a[1][2], a[1][3], aA + 16 * GP * 2 + ks * 32);
        #pragma unroll
        for (int ng = 0; ng < 4; ng++) {
            uint32_t b0, b1, b2, b3;
            ldsm4(b0, b1, b2, b3, aB + ng * (16 * GP * 2) + ks * 32);
            #pragma unroll
            for (int mt = 0; mt < 2; mt++) {
                mma16(acc[mt][ng * 2],     a[mt][0], a[mt][1], a[mt][2], a[mt][3], b0, b1);
                mma16(acc[mt][ng * 2 + 1], a[mt][0], a[mt][1], a[mt][2], a[mt][3], b2, b3);
            }
        }
    }
}

// ---------------- QKV GEMM ---------------------------------------------------------
__global__ __launch_bounds__(256) void qkv_kernel(const float* __restrict__ bias) {
    extern __shared__ __align__(16) __half gsm[];
    int b = blockIdx.z;
    int pm = blockIdx.y * 128;
    int on = blockIdx.x * 128;
    const __half* Ag = g_xnh + (size_t)b * HWn * Cc + (size_t)pm * Cc;
    const __half* Bg = g_qwh + (size_t)on * Cc;

    float acc[2][8][4] = {};
    gemm16(Ag, Bg, gsm, acc);

    int t = threadIdx.x, wid = t >> 5, lane = t & 31, g = lane >> 2, t4 = lane & 3;
    int wm = (wid >> 1) * 32, wn = (wid & 1) * 64;

    if (on < 512) {
        __half* dst = ((on < 256) ? g_q : g_k) + (size_t)b * HWn * Cc;
        int obase = on & 255;
        #pragma unroll
        for (int nt = 0; nt < 8; nt++) {
            int ocol = wn + nt * 8 + t4 * 2;
            float2 bb = *(const float2*)&bias[on + ocol];
            #pragma unroll
            for (int mt = 0; mt < 2; mt++) {
                int p0 = pm + wm + mt * 16 + g;
                __half2 v0 = __floats2half2_rn(acc[mt][nt][0] + bb.x, acc[mt][nt][1] + bb.y);
                __half2 v1 = __floats2half2_rn(acc[mt][nt][2] + bb.x, acc[mt][nt][3] + bb.y);
                *(__half2*)&dst[(size_t)p0 * Cc + obase + ocol]       = v0;
                *(__half2*)&dst[(size_t)(p0 + 8) * Cc + obase + ocol] = v1;
            }
        }
    } else {
        __half* dst = g_vt + (size_t)b * Cc * HWn;
        #pragma unroll
        for (int nt = 0; nt < 8; nt++) {
            int ocol = wn + nt * 8 + t4 * 2;
            int c0 = (on - 512) + ocol;
            float2 bb = *(const float2*)&bias[on + ocol];
            #pragma unroll
            for (int mt = 0; mt < 2; mt++) {
                int p0 = pm + wm + mt * 16 + g;
                dst[(size_t)c0 * HWn + p0]           = __float2half(acc[mt][nt][0] + bb.x);
                dst[(size_t)(c0 + 1) * HWn + p0]     = __float2half(acc[mt][nt][1] + bb.y);
                dst[(size_t)c0 * HWn + p0 + 8]       = __float2half(acc[mt][nt][2] + bb.x);
                dst[(size_t)(c0 + 1) * HWn + p0 + 8] = __float2half(acc[mt][nt][3] + bb.y);
            }
        }
    }
}

// ---------------- flash: monolithic Br=128, warp-local softmax, P in registers ---
__device__ __forceinline__ void copyK16(const __half* Kg, int kt, __half* kb, int t) {
    #pragma unroll
    for (int i = 0; i < 8; i++) {
        int idx = t + 256 * i;
        int row = idx >> 5, pc = idx & 31;
        cp16(kb + row * QPH + pc * 8, Kg + (size_t)(kt * 64 + row) * Cc + pc * 8);
    }
}
__device__ __forceinline__ void copyV16(const __half* Vtg, int kt, __half* vb, int t) {
    #pragma unroll
    for (int i = 0; i < 8; i++) {
        int idx = t + 256 * i;
        int c = idx >> 3, pc = idx & 7;
        cp16(vb + c * VPH + pc * 8, Vtg + (size_t)c * HWn + kt * 64 + pc * 8);
    }
}

__global__ void __launch_bounds__(256, 1) flash_kernel() {
    extern __shared__ __align__(16) __half smh[];
    int b = blockIdx.y;
    int quarter = blockIdx.z;
    int qbase = blockIdx.x * 128;
    int ktbase = quarter * NIT;
    const __half* Qg  = g_q  + (size_t)b * HWn * Cc + (size_t)qbase * Cc;
    const __half* Kg  = g_k  + (size_t)b * HWn * Cc;
    const __half* Vtg = g_vt + (size_t)b * Cc * HWn;

    int t = threadIdx.x;
    int wid = t >> 5, lane = t & 31, g = lane >> 2, t4 = lane & 3;
    uint32_t sb = (uint32_t)__cvta_generic_to_shared(smh);
    uint32_t rowKV = (uint32_t)(((lane >> 4) << 3) + (lane & 7));
    uint32_t colHi = (uint32_t)(((lane >> 3) & 1) << 3);

    int r0 = wid * 16 + g, r1 = r0 + 8;     // this warp's query rows (within tile)
    uint32_t aQ  = sb + (uint32_t)(OFF_Q + (wid * 16 + (lane & 15)) * QPH + (lane >> 4) * 8) * 2;
    uint32_t aK0 = sb + (uint32_t)(OFF_K0 + rowKV * QPH + colHi) * 2;
    uint32_t aK1 = sb + (uint32_t)(OFF_K1 + rowKV * QPH + colHi) * 2;
    uint32_t aV0 = sb + (uint32_t)(OFF_V0 + rowKV * VPH + colHi) * 2;
    uint32_t aV1 = sb + (uint32_t)(OFF_V1 + rowKV * VPH + colHi) * 2;

    float oacc[32][4] = {};
    float M0 = -1e30f, M1 = -1e30f, L0 = 0.f, L1 = 0.f;

    // prologue: K(0), V(0) via cp.async; Q via plain stores
    copyK16(Kg, ktbase, smh + OFF_K0, t);
    copyV16(Vtg, ktbase, smh + OFF_V0, t);
    cpcommit();
    #pragma unroll
    for (int i = 0; i < 16; i++) {
        int idx = t + 256 * i;
        int row = idx >> 5, pc = idx & 31;
        *(uint4*)&smh[OFF_Q + row * QPH + pc * 8] =
            *(const uint4*)(Qg + (size_t)row * Cc + pc * 8);
    }
    cpwait<0>();
    __syncthreads();

    const float SCL = 0.09016844f;   // log2(e)/16

    for (int i = 0; i < NIT; i++) {
        int cur = i & 1;
        if (i < NIT - 1) {
            copyK16(Kg, ktbase + i + 1, smh + (cur ? OFF_K0 : OFF_K1), t);
            copyV16(Vtg, ktbase + i + 1, smh + (cur ? OFF_V0 : OFF_V1), t);
            cpcommit();
        }

        // ---- S[16q x 64m] = Q K^T (warp-local, full chunk) ----
        uint32_t kb = cur ? aK1 : aK0;
        float sacc[4][4] = {};
        #pragma unroll
        for (int ks = 0; ks < 16; ks++) {
            uint32_t q0, q1, q2, q3;
            ldsm4(q0, q1, q2, q3, aQ + ks * 32);
            #pragma unroll
            for (int nt = 0; nt < 4; nt++) {
                uint32_t b0, b1, b2, b3;
                ldsm4(b0, b1, b2, b3, kb + nt * (16 * QPH * 2) + ks * 32);
                mma16(sacc[nt], q0, q1, q2, q3, b0, b1);
                // b2,b3 cover m+8..m+15 -> feed the odd sub-block accumulator
                mma16(sacc[nt], q0, q1, q2, q3, b2, b3);  // placeholder (replaced below)
            }
        }
        // NOTE: the loop above is wrong as written; proper version below.
        (void)sacc;
        break;
    }
    // (unreachable safety)
}

// The above stub is never used; real flash below.
__global__ void __launch_bounds__(256, 1) flash_kernel2() {
    extern __shared__ __align__(16) __half smh[];
    int b = blockIdx.y;
    int quarter = blockIdx.z;
    int qbase = blockIdx.x * 128;
    int ktbase = quarter * NIT;
    const __half* Qg  = g_q  + (size_t)b * HWn * Cc + (size_t)qbase * Cc;
    const __half* Kg  = g_k  + (size_t)b * HWn * Cc;
    const __half* Vtg = g_vt + (size_t)b * Cc * HWn;

    int t = threadIdx.x;
    int wid = t >> 5, lane = t & 31, g = lane >> 2, t4 = lane & 3;
    uint32_t sb = (uint32_t)__cvta_generic_to_shared(smh);
    uint32_t rowKV = (uint32_t)(((lane >> 4) << 3) + (lane & 7));
    uint32_t colHi = (uint32_t)(((lane >> 3) & 1) << 3);

    int r0 = wid * 16 + g, r1 = r0 + 8;
    uint32_t aQ  = sb + (uint32_t)(OFF_Q + (wid * 16 + (lane & 15)) * QPH + (lane >> 4) * 8) * 2;
    uint32_t aK0 = sb + (uint32_t)(OFF_K0 + rowKV * QPH + colHi) * 2;
    uint32_t aK1 = sb + (uint32_t)(OFF_K1 + rowKV * QPH + colHi) * 2;
    uint32_t aV0 = sb + (uint32_t)(OFF_V0 + rowKV * VPH + colHi) * 2;
    uint32_t aV1 = sb + (uint32_t)(OFF_V1 + rowKV * VPH + colHi) * 2;

    float oacc[32][4] = {};
    float M0 = -1e30f, M1 = -1e30f, L0 = 0.f, L1 = 0.f;

    copyK16(Kg, ktbase, smh + OFF_K0, t);
    copyV16(Vtg, ktbase, smh + OFF_V0, t);
    cpcommit();
    #pragma unroll
    for (int i = 0; i < 16; i++) {
        int idx = t + 256 * i;
        int row = idx >> 5, pc = idx & 31;
        *(uint4*)&smh[OFF_Q + row * QPH + pc * 8] =
            *(const uint4*)(Qg + (size_t)row * Cc + pc * 8);
    }
    cpwait<0>();
    __syncthreads();

    const float SCL = 0.09016844f;

    for (int i = 0; i < NIT; i++) {
        int cur = i & 1;
        if (i < NIT - 1) {
            copyK16(Kg, ktbase + i + 1, smh + (cur ? OFF_K0 : OFF_K1), t);
            copyV16(Vtg, ktbase + i + 1, smh + (cur ? OFF_V0 : OFF_V1), t);
            cpcommit();
        }

        // ---- S[16q x 64m]: sacc[nt] = m-block nt*8..nt*8+7 pairs -> 8 blocks of 8m
        uint32_t kb = cur ? aK1 : aK0;
        float sacc[8][4] = {};
        #pragma unroll
        for (int ks = 0; ks < 16; ks++) {
            uint32_t q0, q1, q2, q3;
            ldsm4(q0, q1, q2, q3, aQ + ks * 32);
            #pragma unroll
            for (int nt = 0; nt < 4; nt++) {
                uint32_t b0, b1, b2, b3;
                ldsm4(b0, b1, b2, b3, kb + nt * (16 * QPH * 2) + ks * 32);
                mma16(sacc[nt * 2],     q0, q1, q2, q3, b0, b1);
                mma16(sacc[nt * 2 + 1], q0, q1, q2, q3, b2, b3);
            }
        }

        // ---- warp-local online softmax over the full 64-key chunk ----
        float mx0 = -1e30f, mx1 = -1e30f;
        #pragma unroll
        for (int nt = 0; nt < 8; nt++) {
            #pragma unroll
            for (int jj = 0; jj < 4; jj++) sacc[nt][jj] *= SCL;
            mx0 = fmaxf(mx0, fmaxf(sacc[nt][0], sacc[nt][1]));
            mx1 = fmaxf(mx1, fmaxf(sacc[nt][2], sacc[nt][3]));
        }
        mx0 = fmaxf(mx0, __shfl_xor_sync(0xffffffffu, mx0, 1));
        mx0 = fmaxf(mx0, __shfl_xor_sync(0xffffffffu, mx0, 2));
        mx1 = fmaxf(mx1, __shfl_xor_sync(0xffffffffu, mx1, 1));
        mx1 = fmaxf(mx1, __shfl_xor_sync(0xffffffffu, mx1, 2));
        float Mn0 = fmaxf(M0, mx0), Mn1 = fmaxf(M1, mx1);
        float f0 = exp2f(M0 - Mn0), f1 = exp2f(M1 - Mn1);
        M0 = Mn0; M1 = Mn1;

        float p[8][4];
        float s0 = 0.f, s1 = 0.f;
        #pragma unroll
        for (int nt = 0; nt < 8; nt++) {
            p[nt][0] = exp2f(sacc[nt][0] - Mn0);
            p[nt][1] = exp2f(sacc[nt][1] - Mn0);
            p[nt][2] = exp2f(sacc[nt][2] - Mn1);
            p[nt][3] = exp2f(sacc[nt][3] - Mn1);
            s0 += p[nt][0] + p[nt][1];
            s1 += p[nt][2] + p[nt][3];
        }
        s0 += __shfl_xor_sync(0xffffffffu, s0, 1);
        s0 += __shfl_xor_sync(0xffffffffu, s0, 2);
        s1 += __shfl_xor_sync(0xffffffffu, s1, 1);
        s1 += __shfl_xor_sync(0xffffffffu, s1, 2);
        L0 = L0 * f0 + s0;
        L1 = L1 * f1 + s1;

        // pack P into A-fragments (proven R7 mapping; km = k16 block over m)
        uint32_t pa[4][4];
        #pragma unroll
        for (int km = 0; km < 4; km++) {
            __half2 h0 = __floats2half2_rn(p[2*km][0],   p[2*km][1]);
            __half2 h1 = __floats2half2_rn(p[2*km][2],   p[2*km][3]);
            __half2 h2 = __floats2half2_rn(p[2*km+1][0], p[2*km+1][1]);
            __half2 h3 = __floats2half2_rn(p[2*km+1][2], p[2*km+1][3]);
            pa[km][0] = H2U(h0); pa[km][1] = H2U(h1);
            pa[km][2] = H2U(h2); pa[km][3] = H2U(h3);
        }

        bool nor = (f0 == 1.f) && (f1 == 1.f);
        if (__ballot_sync(0xffffffffu, nor) != 0xffffffffu) {
            #pragma unroll
            for (int u = 0; u < 32; u++) {
                oacc[u][0] *= f0; oacc[u][1] *= f0;
                oacc[u][2] *= f1; oacc[u][3] *= f1;
            }
        }

        // ---- PV: O[16q x 256c] += P[16x64] @ V[64x256] ----
        uint32_t vb = cur ? aV1 : aV0;
        #pragma unroll
        for (int km = 0; km < 4; km++) {
            #pragma unroll
            for (int ct = 0; ct < 16; ct++) {
                uint32_t v0, v1, v2, v3;
                ldsm4(v0, v1, v2, v3, vb + ct * (16 * VPH * 2) + km * 32);
                mma16(oacc[ct * 2],     pa[km][0], pa[km][1], pa[km][2], pa[km][3], v0, v1);
                mma16(oacc[ct * 2 + 1], pa[km][0], pa[km][1], pa[km][2], pa[km][3], v2, v3);
            }
        }

        if (i < NIT - 1) cpwait<0>();
        __syncthreads();
    }

    // epilogue: normalized fp16 partials + (M, L)
    float inv0 = 1.0f / L0, inv1 = 1.0f / L1;
    __half* OP = g_oph + ((size_t)(quarter * Bn + b) * HWn + qbase) * Cc;
    #pragma unroll
    for (int u = 0; u < 32; u++) {
        int ch = u * 8 + t4 * 2;
        __half2 v0 = __floats2half2_rn(oacc[u][0] * inv0, oacc[u][1] * inv0);
        __half2 v1 = __floats2half2_rn(oacc[u][2] * inv1, oacc[u][3] * inv1);
        *(__half2*)&OP[(size_t)r0 * Cc + ch] = v0;
        *(__half2*)&OP[(size_t)r1 * Cc + ch] = v1;
    }
    if (t4 == 0) {
        size_t mlbase = (size_t)(quarter * Bn + b) * HWn + qbase;
        g_ml[mlbase + r0] = make_float2(M0, L0);
        g_ml[mlbase + r1] = make_float2(M1, L1);
    }
}

// ---------------- merge: 4-way weighted sum of normalized fp16 quarters ----------
__global__ __launch_bounds__(256) void merge_kernel() {
    int row = blockIdx.x * 4 + (threadIdx.x >> 6);
    int ch  = (threadIdx.x & 63) * 4;
    const size_t HALF = (size_t)Bn * HWn;

    float2 ml[NSPLIT];
    float M = -1e30f;
    #pragma unroll
    for (int q = 0; q < NSPLIT; q++) {
        ml[q] = g_ml[q * HALF + row];
        M = fmaxf(M, ml[q].x);
    }
    float w[NSPLIT], tot = 0.f;
    #pragma unroll
    for (int q = 0; q < NSPLIT; q++) {
        w[q] = exp2f(ml[q].x - M) * ml[q].y;
        tot += w[q];
    }
    float inv = 1.0f / tot;

    float a0 = 0.f, a1 = 0.f, a2 = 0.f, a3 = 0.f;
    #pragma unroll
    for (int q = 0; q < NSPLIT; q++) {
        float cq = w[q] * inv;
        uint2 pk = *(const uint2*)&g_oph[(size_t)(q * HALF + row) * Cc + ch];
        float2 lo = __half22float2(*(const __half2*)&pk.x);
        float2 hi = __half22float2(*(const __half2*)&pk.y);
        a0 += cq * lo.x; a1 += cq * lo.y;
        a2 += cq * hi.x; a3 += cq * hi.y;
    }
    __half2 h0 = __floats2half2_rn(a0, a1);
    __half2 h1 = __floats2half2_rn(a2, a3);
    uint2 out = { H2U(h0), H2U(h1) };
    *(uint2*)&g_aoh[(size_t)row * Cc + ch] = out;
}

// ---------------- proj GEMM (fp16, 128x64 tiles) + residual -----------------------
__global__ __launch_bounds__(256) void proj_kernel(const float* __restrict__ x,
                                                   const float* __restrict__ pb,
                                                   float* __restrict__ out) {
    extern __shared__ __align__(16) __half gsm[];
    int b = blockIdx.z;
    int om = blockIdx.y * 128;
    int pn = blockIdx.x * 64;
    const __half* Ag = g_pwh + (size_t)om * Cc;
    const __half* Bg = g_aoh + (size_t)b * HWn * Cc + (size_t)pn * Cc;

    int t = threadIdx.x;
    #pragma unroll
    for (int i = 0; i < 16; i++) {
        int idx = t + 256 * i;
        int row = idx >> 5, pc = idx & 31;
        cp16(gsm + row * GP + pc * 8, Ag + (size_t)row * 256 + pc * 8);
    }
    #pragma unroll
    for (int i = 0; i < 8; i++) {
        int idx = t + 256 * i;
        int row = idx >> 5, pc = idx & 31;
        cp16(gsm + 128 * GP + row * GP + pc * 8, Bg + (size_t)row * 256 + pc * 8);
    }
    cpcommit();
    cpwait<0>();
    __syncthreads();

    int wid = t >> 5, lane = t & 31, g = lane >> 2, t4 = lane & 3;
    int wm = (wid >> 1) * 32, wn = (wid & 1) * 32;
    uint32_t sb = (uint32_t)__cvta_generic_to_shared(gsm);
    uint32_t aA = sb + (uint32_t)((wm + (lane & 15)) * GP + (lane >> 4) * 8) * 2;
    uint32_t rowKV = (uint32_t)(((lane >> 4) << 3) + (lane & 7));
    uint32_t colHi = (uint32_t)(((lane >> 3) & 1) << 3);
    uint32_t aB = sb + (uint32_t)(128 * GP + (wn + rowKV) * GP + colHi) * 2;

    float acc[2][4][4] = {};
    #pragma unroll
    for (int ks = 0; ks < 16; ks++) {
        uint32_t a[2][4];
        ldsm4(a[0][0], a[0][1], a[0][2], a[0][3], aA + ks * 32);
        ldsm4(a[1][0], a[1][1], a[1][2], a[1][3], aA + 16 * GP * 2 + ks * 32);
        #pragma unroll
        for (int ng = 0; ng < 2; ng++) {
            uint32_t b0, b1, b2, b3;
            ldsm4(b0, b1, b2, b3, aB + ng * (16 * GP * 2) + ks * 32);
            #pragma unroll
            for (int mt = 0; mt < 2; mt++) {
                mma16(acc[mt][ng * 2],     a[mt][0], a[mt][1], a[mt][2], a[mt][3], b0, b1);
                mma16(acc[mt][ng * 2 + 1], a[mt][0], a[mt][1], a[mt][2], a[mt][3], b2, b3);
            }
        }
    }

    #pragma unroll
    for (int mt = 0; mt < 2; mt++) {
        int o0 = om + wm + mt * 16 + g;
        float b0 = pb[o0], b1 = pb[o0 + 8];
        #pragma unroll
        for (int nt = 0; nt < 4; nt++) {
            int p0 = pn + wn + nt * 8 + t4 * 2;
            size_t off0 = ((size_t)b * Cc + o0) * HWn + p0;
            size_t off1 = ((size_t)b * Cc + o0 + 8) * HWn + p0;
            float2 x0 = *(const float2*)&x[off0];
            float2 x1 = *(const float2*)&x[off1];
            float2 v0 = { acc[mt][nt][0] + b0 + x0.x, acc[mt][nt][1] + b0 + x0.y };
            float2 v1 = { acc[mt][nt][2] + b1 + x1.x, acc[mt][nt][3] + b1 + x1.y };
            *(float2*)&out[off0] = v0;
            *(float2*)&out[off1] = v1;
        }
    }
}

// ---------------- launch ---------------------------------------------------------
extern "C" void kernel_launch(void* const* d_in, const int* in_sizes, int n_in,
                              void* d_out, int out_size) {
    const float* x  = (const float*)d_in[0];
    const float* nw = (const float*)d_in[1];
    const float* nb = (const float*)d_in[2];
    const float* qw = (const float*)d_in[3];
    const float* qb = (const float*)d_in[4];
    const float* pw = (const float*)d_in[5];
    const float* pb = (const float*)d_in[6];
    float* out = (float*)d_out;

    cudaFuncSetAttribute(flash_kernel2, cudaFuncAttributeMaxDynamicSharedMemorySize,
                         SMEM_BYTES);
    cudaFuncSetAttribute(qkv_kernel, cudaFuncAttributeMaxDynamicSharedMemorySize,
                         GEMM_SMEM);
    cudaFuncSetAttribute(proj_kernel, cudaFuncAttributeMaxDynamicSharedMemorySize,
                         PROJ_SMEM);

    gn_stats<<<64 + 192, 1024>>>(x, qw, pw);
    gn_apply<<<512, 512>>>(x, nw, nb);
    qkv_kernel<<<dim3(6, 32, 8), 256, GEMM_SMEM>>>(qb);
    flash_kernel2<<<dim3(32, 8, NSPLIT), 256, SMEM_BYTES>>>();
    merge_kernel<<<Bn * HWn / 4, 256>>>();
    proj_kernel<<<dim3(64, 2, 8), 256, PROJ_SMEM>>>(x, pb, out);
}

// round 17
// speedup vs baseline: 1.3962x; 1.0054x over previous
#include <cuda_runtime.h>
#include <cuda_fp16.h>
#include <cstdint>

#define Bn  8
#define Cc  256
#define HWn 4096

// ---- flash smem layout (half offsets): Br=128, K chunk 64, full V ----
#define QPH 264
#define VPH 72
#define OFF_Q  0
#define OFF_K0 33792                    // 128*264
#define OFF_K1 50688
#define OFF_V0 67584
#define OFF_V1 86016
#define FTOT   104448
#define SMEM_BYTES (FTOT * 2)           // 208896 B

// ---- fp16 GEMM tiles (128x64) ----
#define GP 264
#define GEMM_SMEM (192 * GP * 2)        // 101376 B

#define NSPLIT 4
#define NIT    16

// ---------------- scratch -----------------------------------------------------
__device__ __half g_xnh[(size_t)Bn * HWn * Cc];
__device__ __half g_qwh[768 * 256];
__device__ __half g_pwh[256 * 256];
__device__ __half g_q [(size_t)Bn * HWn * Cc];
__device__ __half g_k [(size_t)Bn * HWn * Cc];
__device__ __half g_vt[(size_t)Bn * Cc * HWn];
__device__ __half g_aoh[(size_t)Bn * HWn * Cc];
__device__ __half g_oph[(size_t)NSPLIT * Bn * HWn * Cc];
__device__ float2 g_ml [(size_t)NSPLIT * Bn * HWn];
__device__ float2 g_mr [64];

// ---------------- helpers ------------------------------------------------------
__device__ __forceinline__ void mma16(float c[4], uint32_t a0, uint32_t a1, uint32_t a2,
                                      uint32_t a3, uint32_t b0, uint32_t b1) {
    asm("mma.sync.aligned.m16n8k16.row.col.f32.f16.f16.f32 "
        "{%0,%1,%2,%3},{%4,%5,%6,%7},{%8,%9},{%0,%1,%2,%3};"
        : "+f"(c[0]), "+f"(c[1]), "+f"(c[2]), "+f"(c[3])
        : "r"(a0), "r"(a1), "r"(a2), "r"(a3), "r"(b0), "r"(b1));
}
__device__ __forceinline__ void ldsm4(uint32_t& r0, uint32_t& r1, uint32_t& r2,
                                      uint32_t& r3, uint32_t a) {
    asm volatile("ldmatrix.sync.aligned.m8n8.x4.shared.b16 {%0,%1,%2,%3}, [%4];"
        : "=r"(r0), "=r"(r1), "=r"(r2), "=r"(r3) : "r"(a));
}
#define H2U(x) (*(const uint32_t*)&(x))

__device__ __forceinline__ void cp16(void* dst, const void* src) {
    uint32_t d = (uint32_t)__cvta_generic_to_shared(dst);
    asm volatile("cp.async.cg.shared.global [%0], [%1], 16;\n" :: "r"(d), "l"(src));
}
__device__ __forceinline__ void cpcommit() { asm volatile("cp.async.commit_group;\n"); }
template<int N> __device__ __forceinline__ void cpwait() {
    asm volatile("cp.async.wait_group %0;\n" :: "n"(N));
}

// ---------------- GN stats (64 blocks) + weight conversion (192 blocks) ----------
__global__ __launch_bounds__(1024) void gn_stats(const float* __restrict__ x,
                                                 const float* __restrict__ qw,
                                                 const float* __restrict__ pw) {
    if (blockIdx.x >= 64) {
        int i = (blockIdx.x - 64) * 1024 + threadIdx.x;
        g_qwh[i] = __float2half(qw[i]);
        if (i < 256 * 256) g_pwh[i] = __float2half(pw[i]);
        return;
    }
    int b = blockIdx.x >> 3, g = blockIdx.x & 7;
    const float4* xb = (const float4*)(x + ((size_t)b * Cc + (size_t)g * 32) * HWn);
    const int N4 = 32 * HWn / 4;

    float s = 0.f, ss = 0.f;
    for (int i = threadIdx.x; i < N4; i += 1024) {
        float4 v = xb[i];
        s  += v.x + v.y + v.z + v.w;
        ss += v.x * v.x + v.y * v.y + v.z * v.z + v.w * v.w;
    }
    __shared__ float rs[32], rss[32];
    int lane = threadIdx.x & 31, wid = threadIdx.x >> 5;
    #pragma unroll
    for (int o = 16; o; o >>= 1) {
        s  += __shfl_down_sync(0xffffffffu, s, o);
        ss += __shfl_down_sync(0xffffffffu, ss, o);
    }
    if (lane == 0) { rs[wid] = s; rss[wid] = ss; }
    __syncthreads();
    if (wid == 0) {
        s  = rs[lane];
        ss = rss[lane];
        #pragma unroll
        for (int o = 16; o; o >>= 1) {
            s  += __shfl_down_sync(0xffffffffu, s, o);
            ss += __shfl_down_sync(0xffffffffu, ss, o);
        }
        if (lane == 0) {
            const float NEL = 32.0f * HWn;
            float mean = s / NEL;
            float var  = ss / NEL - mean * mean;
            g_mr[blockIdx.x] = make_float2(mean, rsqrtf(var + 1e-5f));
        }
    }
}

// ---------------- GN apply (512 blocks) -------------------------------------------
__global__ __launch_bounds__(512) void gn_apply(const float* __restrict__ x,
                                                const float* __restrict__ w,
                                                const float* __restrict__ bv) {
    __shared__ float sm[32][132];
    __shared__ float ws[32], bs[32];
    int bg = blockIdx.x >> 3, slice = blockIdx.x & 7;
    int b = bg >> 3, g = bg & 7;
    const float* xb = x + ((size_t)b * Cc + (size_t)g * 32) * HWn;
    int tid = threadIdx.x;
    float2 mr = g_mr[bg];
    float mean = mr.x, rstd = mr.y;
    if (tid < 32) { ws[tid] = w[g * 32 + tid]; bs[tid] = bv[g * 32 + tid]; }

    __half* out = g_xnh + (size_t)b * HWn * Cc + g * 32;
    int c  = tid >> 4, pl = (tid & 15) * 8;
    int pl2 = tid >> 2, c8 = (tid & 3) * 8;
    int pbase = slice * 512;

    for (int p0 = pbase; p0 < pbase + 512; p0 += 128) {
        float4 v0 = *(const float4*)(xb + (size_t)c * HWn + p0 + pl);
        float4 v1 = *(const float4*)(xb + (size_t)c * HWn + p0 + pl + 4);
        __syncthreads();
        *(float4*)&sm[c][pl]     = v0;
        *(float4*)&sm[c][pl + 4] = v1;
        __syncthreads();
        __half2 h[4];
        #pragma unroll
        for (int jj = 0; jj < 4; jj++) {
            int c0 = c8 + jj * 2;
            float a0 = (sm[c0][pl2]     - mean) * rstd * ws[c0]     + bs[c0];
            float a1 = (sm[c0 + 1][pl2] - mean) * rstd * ws[c0 + 1] + bs[c0 + 1];
            h[jj] = __floats2half2_rn(a0, a1);
        }
        *(uint4*)&out[(size_t)(p0 + pl2) * Cc + c8] = *(uint4*)h;
    }
}

// ---------------- fp16 NT GEMM core (128x64 tile, 2 CTA/SM) ----------------------
// A: 128 rows, B: 64 rows (both row-stride 256 halves). acc[2][4][4].
__device__ __forceinline__ void gemm64(const __half* __restrict__ Ag,
                                       const __half* __restrict__ Bg,
                                       __half* gsm, float acc[2][4][4]) {
    int t = threadIdx.x;
    #pragma unroll
    for (int i = 0; i < 16; i++) {
        int idx = t + 256 * i;
        int row = idx >> 5, pc = idx & 31;
        cp16(gsm + row * GP + pc * 8, Ag + (size_t)row * 256 + pc * 8);
    }
    #pragma unroll
    for (int i = 0; i < 8; i++) {
        int idx = t + 256 * i;
        int row = idx >> 5, pc = idx & 31;
        cp16(gsm + 128 * GP + row * GP + pc * 8, Bg + (size_t)row * 256 + pc * 8);
    }
    cpcommit();
    cpwait<0>();
    __syncthreads();

    int wid = t >> 5, lane = t & 31;
    int wm = (wid >> 1) * 32, wn = (wid & 1) * 32;
    uint32_t sb = (uint32_t)__cvta_generic_to_shared(gsm);
    uint32_t aA = sb + (uint32_t)((wm + (lane & 15)) * GP + (lane >> 4) * 8) * 2;
    uint32_t rowKV = (uint32_t)(((lane >> 4) << 3) + (lane & 7));
    uint32_t colHi = (uint32_t)(((lane >> 3) & 1) << 3);
    uint32_t aB = sb + (uint32_t)(128 * GP + (wn + rowKV) * GP + colHi) * 2;

    #pragma unroll
    for (int ks = 0; ks < 16; ks++) {
        uint32_t a[2][4];
        ldsm4(a[0][0], a[0][1], a[0][2], a[0][3], aA + ks * 32);
        ldsm4(a[1][0], a[1][1], a[1][2], a[1][3], aA + 16 * GP * 2 + ks * 32);
        #pragma unroll
        for (int ng = 0; ng < 2; ng++) {
            uint32_t b0, b1, b2, b3;
            ldsm4(b0, b1, b2, b3, aB + ng * (16 * GP * 2) + ks * 32);
            #pragma unroll
            for (int mt = 0; mt < 2; mt++) {
                mma16(acc[mt][ng * 2],     a[mt][0], a[mt][1], a[mt][2], a[mt][3], b0, b1);
                mma16(acc[mt][ng * 2 + 1], a[mt][0], a[mt][1], a[mt][2], a[mt][3], b2, b3);
            }
        }
    }
}

// ---------------- QKV GEMM (128x64 tiles; q scaled by log2e/16) -------------------
__global__ __launch_bounds__(256) void qkv_kernel(const float* __restrict__ bias) {
    extern __shared__ __align__(16) __half gsm[];
    int b = blockIdx.z;
    int pm = blockIdx.y * 128;
    int on = blockIdx.x * 64;
    const __half* Ag = g_xnh + (size_t)b * HWn * Cc + (size_t)pm * Cc;
    const __half* Bg = g_qwh + (size_t)on * Cc;

    float acc[2][4][4] = {};
    gemm64(Ag, Bg, gsm, acc);

    int t = threadIdx.x, wid = t >> 5, lane = t & 31, g = lane >> 2, t4 = lane & 3;
    int wm = (wid >> 1) * 32, wn = (wid & 1) * 32;

    if (on < 512) {
        __half* dst = ((on < 256) ? g_q : g_k) + (size_t)b * HWn * Cc;
        int obase = on & 255;
        float scl = (on < 256) ? 0.09016844f : 1.0f;   // fold log2(e)/16 into q
        #pragma unroll
        for (int nt = 0; nt < 4; nt++) {
            int ocol = wn + nt * 8 + t4 * 2;
            float2 bb = *(const float2*)&bias[on + ocol];
            #pragma unroll
            for (int mt = 0; mt < 2; mt++) {
                int p0 = pm + wm + mt * 16 + g;
                __half2 v0 = __floats2half2_rn((acc[mt][nt][0] + bb.x) * scl,
                                               (acc[mt][nt][1] + bb.y) * scl);
                __half2 v1 = __floats2half2_rn((acc[mt][nt][2] + bb.x) * scl,
                                               (acc[mt][nt][3] + bb.y) * scl);
                *(__half2*)&dst[(size_t)p0 * Cc + obase + ocol]       = v0;
                *(__half2*)&dst[(size_t)(p0 + 8) * Cc + obase + ocol] = v1;
            }
        }
    } else {
        __half* dst = g_vt + (size_t)b * Cc * HWn;
        #pragma unroll
        for (int nt = 0; nt < 4; nt++) {
            int ocol = wn + nt * 8 + t4 * 2;
            int c0 = (on - 512) + ocol;
            float2 bb = *(const float2*)&bias[on + ocol];
            #pragma unroll
            for (int mt = 0; mt < 2; mt++) {
                int p0 = pm + wm + mt * 16 + g;
                dst[(size_t)c0 * HWn + p0]           = __float2half(acc[mt][nt][0] + bb.x);
                dst[(size_t)(c0 + 1) * HWn + p0]     = __float2half(acc[mt][nt][1] + bb.y);
                dst[(size_t)c0 * HWn + p0 + 8]       = __float2half(acc[mt][nt][2] + bb.x);
                dst[(size_t)(c0 + 1) * HWn + p0 + 8] = __float2half(acc[mt][nt][3] + bb.y);
            }
        }
    }
}

// ---------------- flash: monolithic Br=128, warp-local softmax, P in registers ---
__device__ __forceinline__ void copyK16(const __half* Kg, int kt, __half* kb, int t) {
    #pragma unroll
    for (int i = 0; i < 8; i++) {
        int idx = t + 256 * i;
        int row = idx >> 5, pc = idx & 31;
        cp16(kb + row * QPH + pc * 8, Kg + (size_t)(kt * 64 + row) * Cc + pc * 8);
    }
}
__device__ __forceinline__ void copyV16(const __half* Vtg, int kt, __half* vb, int t) {
    #pragma unroll
    for (int i = 0; i < 8; i++) {
        int idx = t + 256 * i;
        int c = idx >> 3, pc = idx & 7;
        cp16(vb + c * VPH + pc * 8, Vtg + (size_t)c * HWn + kt * 64 + pc * 8);
    }
}

__global__ void __launch_bounds__(256, 1) flash_kernel2() {
    extern __shared__ __align__(16) __half smh[];
    int b = blockIdx.y;
    int quarter = blockIdx.z;
    int qbase = blockIdx.x * 128;
    int ktbase = quarter * NIT;
    const __half* Qg  = g_q  + (size_t)b * HWn * Cc + (size_t)qbase * Cc;
    const __half* Kg  = g_k  + (size_t)b * HWn * Cc;
    const __half* Vtg = g_vt + (size_t)b * Cc * HWn;

    int t = threadIdx.x;
    int wid = t >> 5, lane = t & 31, g = lane >> 2, t4 = lane & 3;
    uint32_t sb = (uint32_t)__cvta_generic_to_shared(smh);
    uint32_t rowKV = (uint32_t)(((lane >> 4) << 3) + (lane & 7));
    uint32_t colHi = (uint32_t)(((lane >> 3) & 1) << 3);

    int r0 = wid * 16 + g, r1 = r0 + 8;
    uint32_t aQ  = sb + (uint32_t)(OFF_Q + (wid * 16 + (lane & 15)) * QPH + (lane >> 4) * 8) * 2;
    uint32_t aK0 = sb + (uint32_t)(OFF_K0 + rowKV * QPH + colHi) * 2;
    uint32_t aK1 = sb + (uint32_t)(OFF_K1 + rowKV * QPH + colHi) * 2;
    uint32_t aV0 = sb + (uint32_t)(OFF_V0 + rowKV * VPH + colHi) * 2;
    uint32_t aV1 = sb + (uint32_t)(OFF_V1 + rowKV * VPH + colHi) * 2;

    float oacc[32][4] = {};
    float M0 = -1e30f, M1 = -1e30f, L0 = 0.f, L1 = 0.f;

    copyK16(Kg, ktbase, smh + OFF_K0, t);
    copyV16(Vtg, ktbase, smh + OFF_V0, t);
    cpcommit();
    #pragma unroll
    for (int i = 0; i < 16; i++) {
        int idx = t + 256 * i;
        int row = idx >> 5, pc = idx & 31;
        *(uint4*)&smh[OFF_Q + row * QPH + pc * 8] =
            *(const uint4*)(Qg + (size_t)row * Cc + pc * 8);
    }
    cpwait<0>();
    __syncthreads();

    for (int i = 0; i < NIT; i++) {
        int cur = i & 1;
        if (i < NIT - 1) {
            copyK16(Kg, ktbase + i + 1, smh + (cur ? OFF_K0 : OFF_K1), t);
            copyV16(Vtg, ktbase + i + 1, smh + (cur ? OFF_V0 : OFF_V1), t);
            cpcommit();
        }

        // ---- S[16q x 64m] (scores pre-scaled via q) ----
        uint32_t kb = cur ? aK1 : aK0;
        float sacc[8][4] = {};
        #pragma unroll
        for (int ks = 0; ks < 16; ks++) {
            uint32_t q0, q1, q2, q3;
            ldsm4(q0, q1, q2, q3, aQ + ks * 32);
            #pragma unroll
            for (int nt = 0; nt < 4; nt++) {
                uint32_t b0, b1, b2, b3;
                ldsm4(b0, b1, b2, b3, kb + nt * (16 * QPH * 2) + ks * 32);
                mma16(sacc[nt * 2],     q0, q1, q2, q3, b0, b1);
                mma16(sacc[nt * 2 + 1], q0, q1, q2, q3, b2, b3);
            }
        }

        // ---- warp-local online softmax ----
        float mx0 = -1e30f, mx1 = -1e30f;
        #pragma unroll
        for (int nt = 0; nt < 8; nt++) {
            mx0 = fmaxf(mx0, fmaxf(sacc[nt][0], sacc[nt][1]));
            mx1 = fmaxf(mx1, fmaxf(sacc[nt][2], sacc[nt][3]));
        }
        mx0 = fmaxf(mx0, __shfl_xor_sync(0xffffffffu, mx0, 1));
        mx0 = fmaxf(mx0, __shfl_xor_sync(0xffffffffu, mx0, 2));
        mx1 = fmaxf(mx1, __shfl_xor_sync(0xffffffffu, mx1, 1));
        mx1 = fmaxf(mx1, __shfl_xor_sync(0xffffffffu, mx1, 2));
        float Mn0 = fmaxf(M0, mx0), Mn1 = fmaxf(M1, mx1);
        float f0 = exp2f(M0 - Mn0), f1 = exp2f(M1 - Mn1);
        M0 = Mn0; M1 = Mn1;

        float p[8][4];
        float s0 = 0.f, s1 = 0.f;
        #pragma unroll
        for (int nt = 0; nt < 8; nt++) {
            p[nt][0] = exp2f(sacc[nt][0] - Mn0);
            p[nt][1] = exp2f(sacc[nt][1] - Mn0);
            p[nt][2] = exp2f(sacc[nt][2] - Mn1);
            p[nt][3] = exp2f(sacc[nt][3] - Mn1);
            s0 += p[nt][0] + p[nt][1];
            s1 += p[nt][2] + p[nt][3];
        }
        s0 += __shfl_xor_sync(0xffffffffu, s0, 1);
        s0 += __shfl_xor_sync(0xffffffffu, s0, 2);
        s1 += __shfl_xor_sync(0xffffffffu, s1, 1);
        s1 += __shfl_xor_sync(0xffffffffu, s1, 2);
        L0 = L0 * f0 + s0;
        L1 = L1 * f1 + s1;

        uint32_t pa[4][4];
        #pragma unroll
        for (int km = 0; km < 4; km++) {
            __half2 h0 = __floats2half2_rn(p[2*km][0],   p[2*km][1]);
            __half2 h1 = __floats2half2_rn(p[2*km][2],   p[2*km][3]);
            __half2 h2 = __floats2half2_rn(p[2*km+1][0], p[2*km+1][1]);
            __half2 h3 = __floats2half2_rn(p[2*km+1][2], p[2*km+1][3]);
            pa[km][0] = H2U(h0); pa[km][1] = H2U(h1);
            pa[km][2] = H2U(h2); pa[km][3] = H2U(h3);
        }

        bool nor = (f0 == 1.f) && (f1 == 1.f);
        if (__ballot_sync(0xffffffffu, nor) != 0xffffffffu) {
            #pragma unroll
            for (int u = 0; u < 32; u++) {
                oacc[u][0] *= f0; oacc[u][1] *= f0;
                oacc[u][2] *= f1; oacc[u][3] *= f1;
            }
        }

        // ---- PV: O[16q x 256c] += P[16x64] @ V[64x256] ----
        uint32_t vb = cur ? aV1 : aV0;
        #pragma unroll
        for (int km = 0; km < 4; km++) {
            #pragma unroll
            for (int ct = 0; ct < 16; ct++) {
                uint32_t v0, v1, v2, v3;
                ldsm4(v0, v1, v2, v3, vb + ct * (16 * VPH * 2) + km * 32);
                mma16(oacc[ct * 2],     pa[km][0], pa[km][1], pa[km][2], pa[km][3], v0, v1);
                mma16(oacc[ct * 2 + 1], pa[km][0], pa[km][1], pa[km][2], pa[km][3], v2, v3);
            }
        }

        if (i < NIT - 1) cpwait<0>();
        __syncthreads();
    }

    float inv0 = 1.0f / L0, inv1 = 1.0f / L1;
    __half* OP = g_oph + ((size_t)(quarter * Bn + b) * HWn + qbase) * Cc;
    #pragma unroll
    for (int u = 0; u < 32; u++) {
        int ch = u * 8 + t4 * 2;
        __half2 v0 = __floats2half2_rn(oacc[u][0] * inv0, oacc[u][1] * inv0);
        __half2 v1 = __floats2half2_rn(oacc[u][2] * inv1, oacc[u][3] * inv1);
        *(__half2*)&OP[(size_t)r0 * Cc + ch] = v0;
        *(__half2*)&OP[(size_t)r1 * Cc + ch] = v1;
    }
    if (t4 == 0) {
        size_t mlbase = (size_t)(quarter * Bn + b) * HWn + qbase;
        g_ml[mlbase + r0] = make_float2(M0, L0);
        g_ml[mlbase + r1] = make_float2(M1, L1);
    }
}

// ---------------- merge: 4-way weighted sum of normalized fp16 quarters ----------
__global__ __launch_bounds__(256) void merge_kernel() {
    int row = blockIdx.x * 4 + (threadIdx.x >> 6);
    int ch  = (threadIdx.x & 63) * 4;
    const size_t HALF = (size_t)Bn * HWn;

    float2 ml[NSPLIT];
    float M = -1e30f;
    #pragma unroll
    for (int q = 0; q < NSPLIT; q++) {
        ml[q] = g_ml[q * HALF + row];
        M = fmaxf(M, ml[q].x);
    }
    float w[NSPLIT], tot = 0.f;
    #pragma unroll
    for (int q = 0; q < NSPLIT; q++) {
        w[q] = exp2f(ml[q].x - M) * ml[q].y;
        tot += w[q];
    }
    float inv = 1.0f / tot;

    float a0 = 0.f, a1 = 0.f, a2 = 0.f, a3 = 0.f;
    #pragma unroll
    for (int q = 0; q < NSPLIT; q++) {
        float cq = w[q] * inv;
        uint2 pk = *(const uint2*)&g_oph[(size_t)(q * HALF + row) * Cc + ch];
        float2 lo = __half22float2(*(const __half2*)&pk.x);
        float2 hi = __half22float2(*(const __half2*)&pk.y);
        a0 += cq * lo.x; a1 += cq * lo.y;
        a2 += cq * hi.x; a3 += cq * hi.y;
    }
    __half2 h0 = __floats2half2_rn(a0, a1);
    __half2 h1 = __floats2half2_rn(a2, a3);
    uint2 out = { H2U(h0), H2U(h1) };
    *(uint2*)&g_aoh[(size_t)row * Cc + ch] = out;
}

// ---------------- proj GEMM (fp16, 128x64 tiles) + residual -----------------------
__global__ __launch_bounds__(256) void proj_kernel(const float* __restrict__ x,
                                                   const float* __restrict__ pb,
                                                   float* __restrict__ out) {
    extern __shared__ __align__(16) __half gsm[];
    int b = blockIdx.z;
    int om = blockIdx.y * 128;
    int pn = blockIdx.x * 64;
    const __half* Ag = g_pwh + (size_t)om * Cc;
    const __half* Bg = g_aoh + (size_t)b * HWn * Cc + (size_t)pn * Cc;

    float acc[2][4][4] = {};
    gemm64(Ag, Bg, gsm, acc);

    int t = threadIdx.x, wid = t >> 5, lane = t & 31, g = lane >> 2, t4 = lane & 3;
    int wm = (wid >> 1) * 32, wn = (wid & 1) * 32;

    #pragma unroll
    for (int mt = 0; mt < 2; mt++) {
        int o0 = om + wm + mt * 16 + g;
        float b0 = pb[o0], b1 = pb[o0 + 8];
        #pragma unroll
        for (int nt = 0; nt < 4; nt++) {
            int p0 = pn + wn + nt * 8 + t4 * 2;
            size_t off0 = ((size_t)b * Cc + o0) * HWn + p0;
            size_t off1 = ((size_t)b * Cc + o0 + 8) * HWn + p0;
            float2 x0 = *(const float2*)&x[off0];
            float2 x1 = *(const float2*)&x[off1];
            float2 v0 = { acc[mt][nt][0] + b0 + x0.x, acc[mt][nt][1] + b0 + x0.y };
            float2 v1 = { acc[mt][nt][2] + b1 + x1.x, acc[mt][nt][3] + b1 + x1.y };
            *(float2*)&out[off0] = v0;
            *(float2*)&out[off1] = v1;
        }
    }
}

// ---------------- launch ---------------------------------------------------------
extern "C" void kernel_launch(void* const* d_in, const int* in_sizes, int n_in,
                              void* d_out, int out_size) {
    const float* x  = (const float*)d_in[0];
    const float* nw = (const float*)d_in[1];
    const float* nb = (const float*)d_in[2];
    const float* qw = (const float*)d_in[3];
    const float* qb = (const float*)d_in[4];
    const float* pw = (const float*)d_in[5];
    const float* pb = (const float*)d_in[6];
    float* out = (float*)d_out;

    cudaFuncSetAttribute(flash_kernel2, cudaFuncAttributeMaxDynamicSharedMemorySize,
                         SMEM_BYTES);
    cudaFuncSetAttribute(qkv_kernel, cudaFuncAttributeMaxDynamicSharedMemorySize,
                         GEMM_SMEM);
    cudaFuncSetAttribute(proj_kernel, cudaFuncAttributeMaxDynamicSharedMemorySize,
                         GEMM_SMEM);

    gn_stats<<<64 + 192, 1024>>>(x, qw, pw);
    gn_apply<<<512, 512>>>(x, nw, nb);
    qkv_kernel<<<dim3(12, 32, 8), 256, GEMM_SMEM>>>(qb);
    flash_kernel2<<<dim3(32, 8, NSPLIT), 256, SMEM_BYTES>>>();
    merge_kernel<<<Bn * HWn / 4, 256>>>();
    proj_kernel<<<dim3(64, 2, 8), 256, GEMM_SMEM>>>(x, pb, out);
}